// round 6
// baseline (speedup 1.0000x reference)
#include <cuda_runtime.h>

#define SLOPE 0.2f
#define NROW  200
#define MAXN  100352
#define MAXE  1000192
#define MAXNB (MAXE / 64)

__device__ float    g_node[(size_t)MAXN * NROW];   // P1|P2|P3|a1|a2|pad  (80MB)
__device__ float    g_partM[64 * MAXNB];
__device__ float    g_partS[64 * MAXNB];
__device__ unsigned g_W2f[8192];   // tf32, fragment-major: [ph][ng][kk][half][lane][4]
__device__ float    g_Wn[64 * NROW];
__device__ float    g_Wa3[64];
__device__ float    g_cvec[64];
__device__ float    g_Mg[64];
__device__ float    g_invS[64];
__device__ float    g_battn;
__device__ int      g_idx64;

__device__ __forceinline__ float lrelu_f(float x) { return x >= 0.f ? x : SLOPE * x; }
__device__ __forceinline__ unsigned f2tf32(float f) {
    unsigned u; asm("cvt.rna.tf32.f32 %0, %1;" : "=r"(u) : "f"(f)); return u;
}
__device__ __forceinline__ void mma_tf32(float* c, unsigned a0, unsigned a1, unsigned a2, unsigned a3,
                                         unsigned b0, unsigned b1) {
    asm volatile("mma.sync.aligned.m16n8k8.row.col.f32.tf32.tf32.f32 "
                 "{%0,%1,%2,%3}, {%4,%5,%6,%7}, {%8,%9}, {%0,%1,%2,%3};"
                 : "+f"(c[0]), "+f"(c[1]), "+f"(c[2]), "+f"(c[3])
                 : "r"(a0), "r"(a1), "r"(a2), "r"(a3), "r"(b0), "r"(b1));
}

__global__ void k_prep(const float* __restrict__ W_attn, const float* __restrict__ b_attn,
                       const float* __restrict__ W_upd,  const float* __restrict__ b_upd,
                       const float* __restrict__ W_edge, const float* __restrict__ b_edge,
                       const float* __restrict__ W_node, const float* __restrict__ b_node,
                       const unsigned* __restrict__ eidx_raw)
{
    int t = threadIdx.x;
    // fragment-major weights: idx = ((((ph*2+ng)*8+kk)*2+half)*32+lane)*4 + j
    for (int idx = t; idx < 8192; idx += 256) {
        int j    = idx & 3;
        int lane = (idx >> 2) & 31;
        int half = (idx >> 7) & 1;
        int kk   = (idx >> 8) & 7;
        int ng   = (idx >> 11) & 1;
        int ph   = (idx >> 12) & 1;
        int g = lane >> 2, q = lane & 3;
        int nt = half * 2 + (j >> 1), b = j & 1;
        int k = kk * 8 + q + b * 4;
        int c = ng * 32 + nt * 8 + g;
        float v = (ph == 0) ? W_upd[(128 + k) * 64 + c] : W_edge[k * 64 + c];
        g_W2f[idx] = f2tf32(v);
    }
    for (int idx = t; idx < 64 * NROW; idx += 256) {
        int k = idx / NROW, c = idx % NROW;
        float v = 0.f;
        if (c < 64)        v = W_upd[k * 64 + c];
        else if (c < 128)  v = W_upd[(64 + k) * 64 + (c - 64)];
        else if (c < 192)  v = W_node[k * 64 + (c - 128)];
        else if (c == 192) v = W_attn[k];
        else if (c == 193) v = W_attn[64 + k];
        g_Wn[idx] = v;
    }
    if (t < 64) {
        g_cvec[t] = b_edge[t] + 2.f * b_node[t];
        g_Wa3[t]  = W_attn[128 + t];
    }
    if (t == 0) {
        g_battn = b_attn[0];
        int is64 = 1;
        for (int i = 0; i < 32; i++)
            if (eidx_raw[2 * i + 1] != 0u) { is64 = 0; break; }
        g_idx64 = is64;
    }
}

__global__ __launch_bounds__(256) void k_node(const float* __restrict__ ne, int N)
{
    __shared__ float sX[32 * 64];
    __shared__ float sW[16 * NROW];
    int t = threadIdx.x;
    int n0 = blockIdx.x * 32;

    for (int i = t; i < 32 * 64; i += 256) {
        int n = n0 + (i >> 6);
        sX[i] = (n < N) ? ne[(size_t)n * 64 + (i & 63)] : 0.f;
    }
    int w = t >> 5, lane = t & 31;
    bool p2 = lane < 18;

    float acc[4][8];
    #pragma unroll
    for (int i = 0; i < 4; i++)
        #pragma unroll
        for (int j = 0; j < 8; j++) acc[i][j] = 0.f;

    for (int stage = 0; stage < 4; stage++) {
        __syncthreads();
        for (int i = t; i < 16 * NROW; i += 256) sW[i] = g_Wn[stage * 16 * NROW + i];
        __syncthreads();
        #pragma unroll 4
        for (int kk = 0; kk < 16; kk++) {
            int k = stage * 16 + kk;
            float4 w0 = *(float4*)&sW[kk * NROW + lane * 4];
            float4 w1 = p2 ? *(float4*)&sW[kk * NROW + 128 + lane * 4]
                           : make_float4(0.f, 0.f, 0.f, 0.f);
            #pragma unroll
            for (int i = 0; i < 4; i++) {
                float x = sX[(w * 4 + i) * 64 + k];
                acc[i][0] += x * w0.x; acc[i][1] += x * w0.y; acc[i][2] += x * w0.z; acc[i][3] += x * w0.w;
                acc[i][4] += x * w1.x; acc[i][5] += x * w1.y; acc[i][6] += x * w1.z; acc[i][7] += x * w1.w;
            }
        }
    }
    #pragma unroll
    for (int i = 0; i < 4; i++) {
        int n = n0 + w * 4 + i;
        if (n >= N) continue;
        float* dst = g_node + (size_t)n * NROW;
        *(float4*)&dst[lane * 4] = make_float4(acc[i][0], acc[i][1], acc[i][2], acc[i][3]);
        if (p2)
            *(float4*)&dst[128 + lane * 4] = make_float4(acc[i][4], acc[i][5], acc[i][6], acc[i][7]);
    }
}

// dummy kernel — keeps k_edge in the fixed ncu capture slot
__global__ void k_mark() { if (threadIdx.x < 64) g_Mg[threadIdx.x] = 0.f; }

// smem (floats): sAu[64*68] tf32 (aliased as sU-tf32 in phase B) | sRes[64*68] | sUf[64*68] | misc 256
#define SA_F (64 * 68)
#define SMEM_F (3 * SA_F + 256)
#define SMEM_BYTES (SMEM_F * 4)

__global__ __launch_bounds__(256, 4) void k_edge(const float* __restrict__ eemb,
                                                 const void*  __restrict__ eidx,
                                                 const float* __restrict__ bupd,
                                                 float*       __restrict__ out,
                                                 int E)
{
    extern __shared__ float smem[];
    unsigned* sAu   = (unsigned*)smem;      // edge tile in tf32; later 'updated' tf32
    float*    sRes  = smem + SA_F;
    float*    sUf   = smem + 2 * SA_F;      // 'updated' fp32 for output path
    float*    sWa   = smem + 3 * SA_F;
    float*    sGate = sWa + 64;
    int*      sSrc  = (int*)(sGate + 64);
    int*      sDst  = sSrc + 64;

    int t = threadIdx.x;
    int e0g = blockIdx.x * 64;
    int idx64 = g_idx64;

    if (t < 128) {
        int j = t & 63;
        int ee = min(e0g + j, E - 1);
        size_t pos = (t < 64) ? (size_t)ee : (size_t)E + (size_t)ee;
        int v = idx64 ? (int)((const long long*)eidx)[pos] : ((const int*)eidx)[pos];
        if (t < 64) sSrc[j] = v; else sDst[j] = v;
    }
    if (t >= 128 && t < 192) sWa[t - 128] = g_Wa3[t - 128];
    for (int i = t; i < 64 * 64; i += 256) {
        int e = i >> 6, k = i & 63;
        int ee = min(e0g + e, E - 1);
        sAu[e * 68 + k] = f2tf32(eemb[(size_t)ee * 64 + k]);
    }
    __syncthreads();

    int lane = t & 31, warp = t >> 5;
    int m0 = (warp & 3) * 16;
    int ng = warp >> 2;            // n-group: cols [ng*32, ng*32+32)
    int n0 = ng * 32;
    int g = lane >> 2, q = lane & 3;
    const uint4* Wf = (const uint4*)g_W2f;   // 2048 uint4

    // ---- MMA1: E3 = A @ Wu3  (A tf32 in smem, B via LDG.128 fragment-major) ----
    float acc[4][4];
    #pragma unroll
    for (int nt = 0; nt < 4; nt++)
        #pragma unroll
        for (int j = 0; j < 4; j++) acc[nt][j] = 0.f;
    #pragma unroll
    for (int kk = 0; kk < 8; kk++) {
        unsigned a0 = sAu[(m0 + g)     * 68 + kk * 8 + q];
        unsigned a1 = sAu[(m0 + g + 8) * 68 + kk * 8 + q];
        unsigned a2 = sAu[(m0 + g)     * 68 + kk * 8 + q + 4];
        unsigned a3 = sAu[(m0 + g + 8) * 68 + kk * 8 + q + 4];
        int b4 = ng * 512 + kk * 64 + lane;        // phase 0
        uint4 w0 = __ldg(&Wf[b4]);
        uint4 w1 = __ldg(&Wf[b4 + 32]);
        mma_tf32(acc[0], a0, a1, a2, a3, w0.x, w0.y);
        mma_tf32(acc[1], a0, a1, a2, a3, w0.z, w0.w);
        mma_tf32(acc[2], a0, a1, a2, a3, w1.x, w1.y);
        mma_tf32(acc[3], a0, a1, a2, a3, w1.z, w1.w);
    }
    #pragma unroll
    for (int nt = 0; nt < 4; nt++) {
        int col = n0 + nt * 8 + q * 2;
        sRes[(m0 + g)     * 68 + col]     = acc[nt][0];
        sRes[(m0 + g)     * 68 + col + 1] = acc[nt][1];
        sRes[(m0 + g + 8) * 68 + col]     = acc[nt][2];
        sRes[(m0 + g + 8) * 68 + col + 1] = acc[nt][3];
    }
    // gate (reads tf32-rounded sAu — completes before the sync below)
    if (t < 64) {
        float s = 0.f;
        #pragma unroll 16
        for (int k = 0; k < 64; k++) s += __uint_as_float(sAu[t * 68 + k]) * sWa[k];
        float a1v = g_node[(size_t)sSrc[t] * NROW + 192];
        float a2v = g_node[(size_t)sDst[t] * NROW + 193];
        sGate[t] = 1.f / (1.f + __expf(-lrelu_f(a1v + a2v + s + g_battn)));
    }
    __syncthreads();

    // ---- Phase B1: updated = gate*(P1s + P2d + E3 + b_u) → sUf (fp32) + sAu (tf32) ----
    int cg = t >> 4, eg = t & 15;
    int c0 = cg * 4, eb = eg * 4;
    float4 buv = *(const float4*)&bupd[c0];
    float4 cvv = *(const float4*)&g_cvec[c0];

    bool val[4];
    #pragma unroll
    for (int i = 0; i < 4; i++) {
        int e = eb + i;
        val[i] = (e0g + e) < E;
        const float* ns = g_node + (size_t)sSrc[e] * NROW;
        const float* nd = g_node + (size_t)sDst[e] * NROW;
        float gt = sGate[e];
        float4 p1 = *(const float4*)(ns + c0);
        float4 p2 = *(const float4*)(nd + 64 + c0);
        float4 e3 = *(const float4*)&sRes[e * 68 + c0];
        float4 u;
        u.x = gt * (p1.x + p2.x + e3.x + buv.x);
        u.y = gt * (p1.y + p2.y + e3.y + buv.y);
        u.z = gt * (p1.z + p2.z + e3.z + buv.z);
        u.w = gt * (p1.w + p2.w + e3.w + buv.w);
        *(float4*)&sUf[e * 68 + c0] = u;
        uint4 ut = make_uint4(f2tf32(u.x), f2tf32(u.y), f2tf32(u.z), f2tf32(u.w));
        *(uint4*)&sAu[e * 68 + c0] = ut;
    }
    __syncthreads();

    // ---- MMA2: T = updated @ W_edge ----
    #pragma unroll
    for (int nt = 0; nt < 4; nt++)
        #pragma unroll
        for (int j = 0; j < 4; j++) acc[nt][j] = 0.f;
    #pragma unroll
    for (int kk = 0; kk < 8; kk++) {
        unsigned a0 = sAu[(m0 + g)     * 68 + kk * 8 + q];
        unsigned a1 = sAu[(m0 + g + 8) * 68 + kk * 8 + q];
        unsigned a2 = sAu[(m0 + g)     * 68 + kk * 8 + q + 4];
        unsigned a3 = sAu[(m0 + g + 8) * 68 + kk * 8 + q + 4];
        int b4 = 1024 + ng * 512 + kk * 64 + lane;  // phase 1
        uint4 w0 = __ldg(&Wf[b4]);
        uint4 w1 = __ldg(&Wf[b4 + 32]);
        mma_tf32(acc[0], a0, a1, a2, a3, w0.x, w0.y);
        mma_tf32(acc[1], a0, a1, a2, a3, w0.z, w0.w);
        mma_tf32(acc[2], a0, a1, a2, a3, w1.x, w1.y);
        mma_tf32(acc[3], a0, a1, a2, a3, w1.z, w1.w);
    }
    __syncthreads();   // sRes (E3) fully consumed in B1; safe to overwrite
    #pragma unroll
    for (int nt = 0; nt < 4; nt++) {
        int col = n0 + nt * 8 + q * 2;
        sRes[(m0 + g)     * 68 + col]     = acc[nt][0];
        sRes[(m0 + g)     * 68 + col + 1] = acc[nt][1];
        sRes[(m0 + g + 8) * 68 + col]     = acc[nt][2];
        sRes[(m0 + g + 8) * 68 + col + 1] = acc[nt][3];
    }
    __syncthreads();

    // ---- Phase B2: z = lrelu(T + P3s + P3d + cvec); block softmax; store ----
    float zs[4][4];
    #pragma unroll
    for (int i = 0; i < 4; i++) {
        int e = eb + i;
        const float* ns = g_node + (size_t)sSrc[e] * NROW;
        const float* nd = g_node + (size_t)sDst[e] * NROW;
        float4 p3s = *(const float4*)(ns + 128 + c0);
        float4 p3d = *(const float4*)(nd + 128 + c0);
        float4 tv  = *(const float4*)&sRes[e * 68 + c0];
        zs[i][0] = lrelu_f(tv.x + p3s.x + p3d.x + cvv.x);
        zs[i][1] = lrelu_f(tv.y + p3s.y + p3d.y + cvv.y);
        zs[i][2] = lrelu_f(tv.z + p3s.z + p3d.z + cvv.z);
        zs[i][3] = lrelu_f(tv.w + p3s.w + p3d.w + cvv.w);
    }

    float m[4];
    #pragma unroll
    for (int j = 0; j < 4; j++) {
        float mm = -1e30f;
        #pragma unroll
        for (int i = 0; i < 4; i++) if (val[i]) mm = fmaxf(mm, zs[i][j]);
        m[j] = mm;
    }
    #pragma unroll
    for (int off = 8; off > 0; off >>= 1)
        #pragma unroll
        for (int j = 0; j < 4; j++)
            m[j] = fmaxf(m[j], __shfl_xor_sync(0xffffffffu, m[j], off, 16));

    float sv[4] = {0.f, 0.f, 0.f, 0.f};
    #pragma unroll
    for (int i = 0; i < 4; i++) {
        int e = eb + i;
        float ex0 = __expf(zs[i][0] - m[0]);
        float ex1 = __expf(zs[i][1] - m[1]);
        float ex2 = __expf(zs[i][2] - m[2]);
        float ex3 = __expf(zs[i][3] - m[3]);
        if (val[i]) {
            sv[0] += ex0; sv[1] += ex1; sv[2] += ex2; sv[3] += ex3;
            float4 u = *(const float4*)&sUf[e * 68 + c0];
            float4 o = make_float4(u.x * ex0, u.y * ex1, u.z * ex2, u.w * ex3);
            *(float4*)&out[(size_t)(e0g + e) * 64 + c0] = o;
        }
    }
    #pragma unroll
    for (int off = 8; off > 0; off >>= 1)
        #pragma unroll
        for (int j = 0; j < 4; j++)
            sv[j] += __shfl_xor_sync(0xffffffffu, sv[j], off, 16);

    if (eg == 0) {
        #pragma unroll
        for (int j = 0; j < 4; j++) {
            g_partM[(c0 + j) * MAXNB + blockIdx.x] = m[j];
            g_partS[(c0 + j) * MAXNB + blockIdx.x] = sv[j];
        }
    }
}

__global__ void k_combine(int NB)
{
    int c = blockIdx.x, t = threadIdx.x;
    float m = -1e30f, s = 0.f;
    for (int b = t; b < NB; b += 256) {
        float mb = g_partM[c * MAXNB + b], sb = g_partS[c * MAXNB + b];
        float M2 = fmaxf(m, mb);
        s = s * __expf(m - M2) + sb * __expf(mb - M2);
        m = M2;
    }
    __shared__ float sm[256], ss[256];
    sm[t] = m; ss[t] = s; __syncthreads();
    for (int off = 128; off > 0; off >>= 1) {
        if (t < off) {
            float M2 = fmaxf(sm[t], sm[t + off]);
            ss[t] = ss[t] * __expf(sm[t] - M2) + ss[t + off] * __expf(sm[t + off] - M2);
            sm[t] = M2;
        }
        __syncthreads();
    }
    if (t == 0) { g_Mg[c] = sm[0]; g_invS[c] = 1.f / ss[0]; }
}

__global__ void k_pass2(float4* __restrict__ out, int total4)
{
    int i = blockIdx.x * 256 + threadIdx.x;
    if (i >= total4) return;
    int c0 = (i * 4) & 63;
    int b  = i >> 10;
    float4 o = out[i];
    o.x *= __expf(g_partM[(c0 + 0) * MAXNB + b] - g_Mg[c0 + 0]) * g_invS[c0 + 0];
    o.y *= __expf(g_partM[(c0 + 1) * MAXNB + b] - g_Mg[c0 + 1]) * g_invS[c0 + 1];
    o.z *= __expf(g_partM[(c0 + 2) * MAXNB + b] - g_Mg[c0 + 2]) * g_invS[c0 + 2];
    o.w *= __expf(g_partM[(c0 + 3) * MAXNB + b] - g_Mg[c0 + 3]) * g_invS[c0 + 3];
    out[i] = o;
}

extern "C" void kernel_launch(void* const* d_in, const int* in_sizes, int n_in,
                              void* d_out, int out_size)
{
    const float* eemb = (const float*)d_in[0];
    const float* ne   = (const float*)d_in[2];
    const float* Wa   = (const float*)d_in[3];
    const float* ba   = (const float*)d_in[4];
    const float* Wu   = (const float*)d_in[5];
    const float* bu   = (const float*)d_in[6];
    const float* We   = (const float*)d_in[7];
    const float* be   = (const float*)d_in[8];
    const float* Wn   = (const float*)d_in[9];
    const float* bn   = (const float*)d_in[10];
    const void*  eidx = d_in[11];
    float* out = (float*)d_out;

    int E = in_sizes[0] / 64;
    int N = in_sizes[2] / 64;
    int NB = (E + 63) / 64;

    cudaFuncSetAttribute(k_edge, cudaFuncAttributeMaxDynamicSharedMemorySize, SMEM_BYTES);

    k_prep<<<1, 256>>>(Wa, ba, Wu, bu, We, be, Wn, bn, (const unsigned*)eidx);
    k_node<<<(N + 31) / 32, 256>>>(ne, N);
    k_mark<<<1, 64>>>();
    k_edge<<<NB, 256, SMEM_BYTES>>>(eemb, eidx, bu, out, E);
    k_combine<<<64, 256>>>(NB);
    int total4 = E * 16;
    k_pass2<<<(total4 + 255) / 256, 256>>>((float4*)out, total4);
}

// round 7
// speedup vs baseline: 1.2540x; 1.2540x over previous
#include <cuda_runtime.h>

#define SLOPE 0.2f
#define NROW  200
#define MAXN  100352
#define MAXE  1000192
#define MAXNB (MAXE / 64)

__device__ float    g_node[(size_t)MAXN * NROW];   // P1|P2|P3|a1|a2|pad  (80MB)
__device__ float    g_partM[64 * MAXNB];
__device__ float    g_partS[64 * MAXNB];
__device__ unsigned g_W2f[8192];   // tf32, fragment-major: [ph][ng][kk][half][lane][4]
__device__ float    g_Wn[64 * NROW];
__device__ float    g_Wa3[64];
__device__ float    g_cvec[64];
__device__ float    g_Mg[64];
__device__ float    g_invS[64];
__device__ float    g_battn;
__device__ int      g_idx64;

__device__ __forceinline__ float lrelu_f(float x) { return x >= 0.f ? x : SLOPE * x; }
__device__ __forceinline__ unsigned f2tf32(float f) {
    unsigned u; asm("cvt.rna.tf32.f32 %0, %1;" : "=r"(u) : "f"(f)); return u;
}
__device__ __forceinline__ void mma_tf32(float* c, unsigned a0, unsigned a1, unsigned a2, unsigned a3,
                                         unsigned b0, unsigned b1) {
    asm volatile("mma.sync.aligned.m16n8k8.row.col.f32.tf32.tf32.f32 "
                 "{%0,%1,%2,%3}, {%4,%5,%6,%7}, {%8,%9}, {%0,%1,%2,%3};"
                 : "+f"(c[0]), "+f"(c[1]), "+f"(c[2]), "+f"(c[3])
                 : "r"(a0), "r"(a1), "r"(a2), "r"(a3), "r"(b0), "r"(b1));
}

__global__ void k_prep(const float* __restrict__ W_attn, const float* __restrict__ b_attn,
                       const float* __restrict__ W_upd,  const float* __restrict__ b_upd,
                       const float* __restrict__ W_edge, const float* __restrict__ b_edge,
                       const float* __restrict__ W_node, const float* __restrict__ b_node,
                       const unsigned* __restrict__ eidx_raw)
{
    int t = threadIdx.x;
    for (int idx = t; idx < 8192; idx += 256) {
        int j    = idx & 3;
        int lane = (idx >> 2) & 31;
        int half = (idx >> 7) & 1;
        int kk   = (idx >> 8) & 7;
        int ng   = (idx >> 11) & 1;
        int ph   = (idx >> 12) & 1;
        int g = lane >> 2, q = lane & 3;
        int nt = half * 2 + (j >> 1), b = j & 1;
        int k = kk * 8 + q + b * 4;
        int c = ng * 32 + nt * 8 + g;
        float v = (ph == 0) ? W_upd[(128 + k) * 64 + c] : W_edge[k * 64 + c];
        g_W2f[idx] = f2tf32(v);
    }
    for (int idx = t; idx < 64 * NROW; idx += 256) {
        int k = idx / NROW, c = idx % NROW;
        float v = 0.f;
        if (c < 64)        v = W_upd[k * 64 + c];
        else if (c < 128)  v = W_upd[(64 + k) * 64 + (c - 64)];
        else if (c < 192)  v = W_node[k * 64 + (c - 128)];
        else if (c == 192) v = W_attn[k];
        else if (c == 193) v = W_attn[64 + k];
        g_Wn[idx] = v;
    }
    if (t < 64) {
        g_cvec[t] = b_edge[t] + 2.f * b_node[t];
        g_Wa3[t]  = W_attn[128 + t];
    }
    if (t == 0) {
        g_battn = b_attn[0];
        int is64 = 1;
        for (int i = 0; i < 32; i++)
            if (eidx_raw[2 * i + 1] != 0u) { is64 = 0; break; }
        g_idx64 = is64;
    }
}

__global__ __launch_bounds__(256) void k_node(const float* __restrict__ ne, int N)
{
    __shared__ float sX[32 * 64];
    __shared__ float sW[16 * NROW];
    int t = threadIdx.x;
    int n0 = blockIdx.x * 32;

    for (int i = t; i < 32 * 64; i += 256) {
        int n = n0 + (i >> 6);
        sX[i] = (n < N) ? ne[(size_t)n * 64 + (i & 63)] : 0.f;
    }
    int w = t >> 5, lane = t & 31;
    bool p2 = lane < 18;

    float acc[4][8];
    #pragma unroll
    for (int i = 0; i < 4; i++)
        #pragma unroll
        for (int j = 0; j < 8; j++) acc[i][j] = 0.f;

    for (int stage = 0; stage < 4; stage++) {
        __syncthreads();
        for (int i = t; i < 16 * NROW; i += 256) sW[i] = g_Wn[stage * 16 * NROW + i];
        __syncthreads();
        #pragma unroll 4
        for (int kk = 0; kk < 16; kk++) {
            int k = stage * 16 + kk;
            float4 w0 = *(float4*)&sW[kk * NROW + lane * 4];
            float4 w1 = p2 ? *(float4*)&sW[kk * NROW + 128 + lane * 4]
                           : make_float4(0.f, 0.f, 0.f, 0.f);
            #pragma unroll
            for (int i = 0; i < 4; i++) {
                float x = sX[(w * 4 + i) * 64 + k];
                acc[i][0] += x * w0.x; acc[i][1] += x * w0.y; acc[i][2] += x * w0.z; acc[i][3] += x * w0.w;
                acc[i][4] += x * w1.x; acc[i][5] += x * w1.y; acc[i][6] += x * w1.z; acc[i][7] += x * w1.w;
            }
        }
    }
    #pragma unroll
    for (int i = 0; i < 4; i++) {
        int n = n0 + w * 4 + i;
        if (n >= N) continue;
        float* dst = g_node + (size_t)n * NROW;
        *(float4*)&dst[lane * 4] = make_float4(acc[i][0], acc[i][1], acc[i][2], acc[i][3]);
        if (p2)
            *(float4*)&dst[128 + lane * 4] = make_float4(acc[i][4], acc[i][5], acc[i][6], acc[i][7]);
    }
}

// dummy kernel — keeps k_edge in the fixed ncu capture slot
__global__ void k_mark() { if (threadIdx.x < 64) g_Mg[threadIdx.x] = 0.f; }

// smem (floats): sAu[64*68] tf32 | sRes[64*68] | sUf[64*64] | sPM[8*68] | sPS[8*68] | misc
#define SA_F  (64 * 68)
#define SUF_F (64 * 64)
#define SP_F  (8 * 68)
#define SMEM_F (2 * SA_F + SUF_F + 2 * SP_F + 256)
#define SMEM_BYTES (SMEM_F * 4)

__global__ __launch_bounds__(256, 4) void k_edge(const float* __restrict__ eemb,
                                                 const void*  __restrict__ eidx,
                                                 const float* __restrict__ bupd,
                                                 float*       __restrict__ out,
                                                 int E)
{
    extern __shared__ float smem[];
    unsigned* sAu   = (unsigned*)smem;       // edge tile tf32; later 'updated' tf32
    float*    sRes  = smem + SA_F;
    float*    sUf   = smem + 2 * SA_F;       // 'updated' fp32 (pitch 64)
    float*    sPM   = smem + 2 * SA_F + SUF_F;
    float*    sPS   = sPM + SP_F;
    float*    sWa   = sPS + SP_F;
    float*    sGate = sWa + 64;
    int*      sSrc  = (int*)(sGate + 64);
    int*      sDst  = sSrc + 64;

    int t = threadIdx.x;
    int e0g = blockIdx.x * 64;
    int idx64 = g_idx64;

    if (t < 128) {
        int j = t & 63;
        int ee = min(e0g + j, E - 1);
        size_t pos = (t < 64) ? (size_t)ee : (size_t)E + (size_t)ee;
        int v = idx64 ? (int)((const long long*)eidx)[pos] : ((const int*)eidx)[pos];
        if (t < 64) sSrc[j] = v; else sDst[j] = v;
    }
    if (t >= 128 && t < 192) sWa[t - 128] = g_Wa3[t - 128];
    for (int i = t; i < 64 * 64; i += 256) {
        int e = i >> 6, k = i & 63;
        int ee = min(e0g + e, E - 1);
        sAu[e * 68 + k] = f2tf32(eemb[(size_t)ee * 64 + k]);
    }
    __syncthreads();

    int lane = t & 31, warp = t >> 5;
    int m0 = (warp & 3) * 16;
    int ng = warp >> 2;
    int n0 = ng * 32;
    int g = lane >> 2, q = lane & 3;
    const uint4* Wf = (const uint4*)g_W2f;

    // ---- MMA1: E3 = A @ Wu3 ----
    float acc[4][4];
    #pragma unroll
    for (int nt = 0; nt < 4; nt++)
        #pragma unroll
        for (int j = 0; j < 4; j++) acc[nt][j] = 0.f;
    #pragma unroll
    for (int kk = 0; kk < 8; kk++) {
        unsigned a0 = sAu[(m0 + g)     * 68 + kk * 8 + q];
        unsigned a1 = sAu[(m0 + g + 8) * 68 + kk * 8 + q];
        unsigned a2 = sAu[(m0 + g)     * 68 + kk * 8 + q + 4];
        unsigned a3 = sAu[(m0 + g + 8) * 68 + kk * 8 + q + 4];
        int b4 = ng * 512 + kk * 64 + lane;
        uint4 w0 = __ldg(&Wf[b4]);
        uint4 w1 = __ldg(&Wf[b4 + 32]);
        mma_tf32(acc[0], a0, a1, a2, a3, w0.x, w0.y);
        mma_tf32(acc[1], a0, a1, a2, a3, w0.z, w0.w);
        mma_tf32(acc[2], a0, a1, a2, a3, w1.x, w1.y);
        mma_tf32(acc[3], a0, a1, a2, a3, w1.z, w1.w);
    }
    #pragma unroll
    for (int nt = 0; nt < 4; nt++) {
        int col = n0 + nt * 8 + q * 2;
        sRes[(m0 + g)     * 68 + col]     = acc[nt][0];
        sRes[(m0 + g)     * 68 + col + 1] = acc[nt][1];
        sRes[(m0 + g + 8) * 68 + col]     = acc[nt][2];
        sRes[(m0 + g + 8) * 68 + col + 1] = acc[nt][3];
    }
    // gate
    if (t < 64) {
        float s = 0.f;
        #pragma unroll 16
        for (int k = 0; k < 64; k++) s += __uint_as_float(sAu[t * 68 + k]) * sWa[k];
        float a1v = g_node[(size_t)sSrc[t] * NROW + 192];
        float a2v = g_node[(size_t)sDst[t] * NROW + 193];
        sGate[t] = 1.f / (1.f + __expf(-lrelu_f(a1v + a2v + s + g_battn)));
    }
    __syncthreads();

    // ---- Phase B1 (coalesced): warp w → edges w*8..w*8+7, lane → channels 2l,2l+1 ----
    int c = lane * 2;
    int ebase = warp * 8;
    float2 bu2 = make_float2(bupd[c], bupd[c + 1]);
    float2 cv2 = make_float2(g_cvec[c], g_cvec[c + 1]);

    #pragma unroll
    for (int i0 = 0; i0 < 8; i0 += 4) {
        float2 P1[4], P2[4];
        #pragma unroll
        for (int i = 0; i < 4; i++) {
            int e = ebase + i0 + i;
            P1[i] = *(const float2*)(g_node + (size_t)sSrc[e] * NROW + c);
            P2[i] = *(const float2*)(g_node + (size_t)sDst[e] * NROW + 64 + c);
        }
        #pragma unroll
        for (int i = 0; i < 4; i++) {
            int e = ebase + i0 + i;
            float gt = sGate[e];
            float2 e3 = *(const float2*)&sRes[e * 68 + c];
            float2 u;
            u.x = gt * (P1[i].x + P2[i].x + e3.x + bu2.x);
            u.y = gt * (P1[i].y + P2[i].y + e3.y + bu2.y);
            *(float2*)&sUf[e * 64 + c] = u;
            uint2 ut = make_uint2(f2tf32(u.x), f2tf32(u.y));
            *(uint2*)&sAu[e * 68 + c] = ut;
        }
    }
    __syncthreads();

    // ---- MMA2: T = updated @ W_edge ----
    #pragma unroll
    for (int nt = 0; nt < 4; nt++)
        #pragma unroll
        for (int j = 0; j < 4; j++) acc[nt][j] = 0.f;
    #pragma unroll
    for (int kk = 0; kk < 8; kk++) {
        unsigned a0 = sAu[(m0 + g)     * 68 + kk * 8 + q];
        unsigned a1 = sAu[(m0 + g + 8) * 68 + kk * 8 + q];
        unsigned a2 = sAu[(m0 + g)     * 68 + kk * 8 + q + 4];
        unsigned a3 = sAu[(m0 + g + 8) * 68 + kk * 8 + q + 4];
        int b4 = 1024 + ng * 512 + kk * 64 + lane;
        uint4 w0 = __ldg(&Wf[b4]);
        uint4 w1 = __ldg(&Wf[b4 + 32]);
        mma_tf32(acc[0], a0, a1, a2, a3, w0.x, w0.y);
        mma_tf32(acc[1], a0, a1, a2, a3, w0.z, w0.w);
        mma_tf32(acc[2], a0, a1, a2, a3, w1.x, w1.y);
        mma_tf32(acc[3], a0, a1, a2, a3, w1.z, w1.w);
    }
    __syncthreads();   // B1's sRes reads complete; safe to overwrite
    #pragma unroll
    for (int nt = 0; nt < 4; nt++) {
        int col = n0 + nt * 8 + q * 2;
        sRes[(m0 + g)     * 68 + col]     = acc[nt][0];
        sRes[(m0 + g)     * 68 + col + 1] = acc[nt][1];
        sRes[(m0 + g + 8) * 68 + col]     = acc[nt][2];
        sRes[(m0 + g + 8) * 68 + col + 1] = acc[nt][3];
    }
    __syncthreads();

    // ---- Phase B2 (coalesced): z, per-warp softmax partials ----
    float2 zs[8];
    #pragma unroll
    for (int i0 = 0; i0 < 8; i0 += 4) {
        float2 P3s[4], P3d[4];
        #pragma unroll
        for (int i = 0; i < 4; i++) {
            int e = ebase + i0 + i;
            P3s[i] = *(const float2*)(g_node + (size_t)sSrc[e] * NROW + 128 + c);
            P3d[i] = *(const float2*)(g_node + (size_t)sDst[e] * NROW + 128 + c);
        }
        #pragma unroll
        for (int i = 0; i < 4; i++) {
            int e = ebase + i0 + i;
            bool v = (e0g + e) < E;
            float2 tv = *(const float2*)&sRes[e * 68 + c];
            float zx = lrelu_f(tv.x + P3s[i].x + P3d[i].x + cv2.x);
            float zy = lrelu_f(tv.y + P3s[i].y + P3d[i].y + cv2.y);
            zs[i0 + i] = v ? make_float2(zx, zy) : make_float2(-1e30f, -1e30f);
        }
    }
    // per-thread max over 8 edges
    float2 ml = make_float2(-1e30f, -1e30f);
    #pragma unroll
    for (int i = 0; i < 8; i++) {
        ml.x = fmaxf(ml.x, zs[i].x);
        ml.y = fmaxf(ml.y, zs[i].y);
    }
    *(float2*)&sPM[warp * 68 + c] = ml;
    __syncthreads();
    float2 mb = make_float2(-1e30f, -1e30f);
    #pragma unroll
    for (int w2 = 0; w2 < 8; w2++) {
        mb.x = fmaxf(mb.x, sPM[w2 * 68 + c]);
        mb.y = fmaxf(mb.y, sPM[w2 * 68 + c + 1]);
    }
    // exp, store out, local sums
    float2 sl = make_float2(0.f, 0.f);
    #pragma unroll
    for (int i = 0; i < 8; i++) {
        int e = ebase + i;
        if ((e0g + e) < E) {
            float ex = __expf(zs[i].x - mb.x);
            float ey = __expf(zs[i].y - mb.y);
            sl.x += ex; sl.y += ey;
            float2 u = *(const float2*)&sUf[e * 64 + c];
            float2 o = make_float2(u.x * ex, u.y * ey);
            *(float2*)&out[(size_t)(e0g + e) * 64 + c] = o;
        }
    }
    *(float2*)&sPS[warp * 68 + c] = sl;
    __syncthreads();
    if (warp == 0) {
        float sx = 0.f, sy = 0.f;
        #pragma unroll
        for (int w2 = 0; w2 < 8; w2++) {
            sx += sPS[w2 * 68 + c];
            sy += sPS[w2 * 68 + c + 1];
        }
        g_partM[c * MAXNB + blockIdx.x]       = mb.x;
        g_partM[(c + 1) * MAXNB + blockIdx.x] = mb.y;
        g_partS[c * MAXNB + blockIdx.x]       = sx;
        g_partS[(c + 1) * MAXNB + blockIdx.x] = sy;
    }
}

__global__ void k_combine(int NB)
{
    int c = blockIdx.x, t = threadIdx.x;
    float m = -1e30f, s = 0.f;
    for (int b = t; b < NB; b += 256) {
        float mb = g_partM[c * MAXNB + b], sb = g_partS[c * MAXNB + b];
        float M2 = fmaxf(m, mb);
        s = s * __expf(m - M2) + sb * __expf(mb - M2);
        m = M2;
    }
    __shared__ float sm[256], ss[256];
    sm[t] = m; ss[t] = s; __syncthreads();
    for (int off = 128; off > 0; off >>= 1) {
        if (t < off) {
            float M2 = fmaxf(sm[t], sm[t + off]);
            ss[t] = ss[t] * __expf(sm[t] - M2) + ss[t + off] * __expf(sm[t + off] - M2);
            sm[t] = M2;
        }
        __syncthreads();
    }
    if (t == 0) { g_Mg[c] = sm[0]; g_invS[c] = 1.f / ss[0]; }
}

__global__ void k_pass2(float4* __restrict__ out, int total4)
{
    int i = blockIdx.x * 256 + threadIdx.x;
    if (i >= total4) return;
    int c0 = (i * 4) & 63;
    int b  = i >> 10;
    float4 o = out[i];
    o.x *= __expf(g_partM[(c0 + 0) * MAXNB + b] - g_Mg[c0 + 0]) * g_invS[c0 + 0];
    o.y *= __expf(g_partM[(c0 + 1) * MAXNB + b] - g_Mg[c0 + 1]) * g_invS[c0 + 1];
    o.z *= __expf(g_partM[(c0 + 2) * MAXNB + b] - g_Mg[c0 + 2]) * g_invS[c0 + 2];
    o.w *= __expf(g_partM[(c0 + 3) * MAXNB + b] - g_Mg[c0 + 3]) * g_invS[c0 + 3];
    out[i] = o;
}

extern "C" void kernel_launch(void* const* d_in, const int* in_sizes, int n_in,
                              void* d_out, int out_size)
{
    const float* eemb = (const float*)d_in[0];
    const float* ne   = (const float*)d_in[2];
    const float* Wa   = (const float*)d_in[3];
    const float* ba   = (const float*)d_in[4];
    const float* Wu   = (const float*)d_in[5];
    const float* bu   = (const float*)d_in[6];
    const float* We   = (const float*)d_in[7];
    const float* be   = (const float*)d_in[8];
    const float* Wn   = (const float*)d_in[9];
    const float* bn   = (const float*)d_in[10];
    const void*  eidx = d_in[11];
    float* out = (float*)d_out;

    int E = in_sizes[0] / 64;
    int N = in_sizes[2] / 64;
    int NB = (E + 63) / 64;

    cudaFuncSetAttribute(k_edge, cudaFuncAttributeMaxDynamicSharedMemorySize, SMEM_BYTES);

    k_prep<<<1, 256>>>(Wa, ba, Wu, bu, We, be, Wn, bn, (const unsigned*)eidx);
    k_node<<<(N + 31) / 32, 256>>>(ne, N);
    k_mark<<<1, 64>>>();
    k_edge<<<NB, 256, SMEM_BYTES>>>(eemb, eidx, bu, out, E);
    k_combine<<<64, 256>>>(NB);
    int total4 = E * 16;
    k_pass2<<<(total4 + 255) / 256, 256>>>((float4*)out, total4);
}

// round 8
// speedup vs baseline: 1.2704x; 1.0132x over previous
#include <cuda_runtime.h>

#define SLOPE 0.2f
#define NROW  200
#define NRB   (NROW * 4)          // node row bytes
#define MAXN  100352
#define MAXE  1000192
#define MAXNB (MAXE / 64)

__device__ float    g_node[(size_t)MAXN * NROW];   // P1|P2|P3|a1|a2|pad  (80MB)
__device__ float    g_partM[64 * MAXNB];
__device__ float    g_partS[64 * MAXNB];
__device__ unsigned g_W2f[8192];   // tf32, fragment-major: [ph][ng][kk][half][lane][4]
__device__ float    g_Wn[64 * NROW];
__device__ float    g_Wa3[64];
__device__ float    g_cvec[64];
__device__ float    g_Mg[64];
__device__ float    g_invS[64];
__device__ float    g_battn;
__device__ int      g_idx64;

__device__ __forceinline__ float lrelu_f(float x) { return x >= 0.f ? x : SLOPE * x; }
__device__ __forceinline__ unsigned f2tf32(float f) {
    unsigned u; asm("cvt.rna.tf32.f32 %0, %1;" : "=r"(u) : "f"(f)); return u;
}
__device__ __forceinline__ void mma_tf32(float* c, unsigned a0, unsigned a1, unsigned a2, unsigned a3,
                                         unsigned b0, unsigned b1) {
    asm volatile("mma.sync.aligned.m16n8k8.row.col.f32.tf32.tf32.f32 "
                 "{%0,%1,%2,%3}, {%4,%5,%6,%7}, {%8,%9}, {%0,%1,%2,%3};"
                 : "+f"(c[0]), "+f"(c[1]), "+f"(c[2]), "+f"(c[3])
                 : "r"(a0), "r"(a1), "r"(a2), "r"(a3), "r"(b0), "r"(b1));
}

__global__ void k_prep(const float* __restrict__ W_attn, const float* __restrict__ b_attn,
                       const float* __restrict__ W_upd,  const float* __restrict__ b_upd,
                       const float* __restrict__ W_edge, const float* __restrict__ b_edge,
                       const float* __restrict__ W_node, const float* __restrict__ b_node,
                       const unsigned* __restrict__ eidx_raw)
{
    int t = threadIdx.x;
    for (int idx = t; idx < 8192; idx += 256) {
        int j    = idx & 3;
        int lane = (idx >> 2) & 31;
        int half = (idx >> 7) & 1;
        int kk   = (idx >> 8) & 7;
        int ng   = (idx >> 11) & 1;
        int ph   = (idx >> 12) & 1;
        int g = lane >> 2, q = lane & 3;
        int nt = half * 2 + (j >> 1), b = j & 1;
        int k = kk * 8 + q + b * 4;
        int c = ng * 32 + nt * 8 + g;
        float v = (ph == 0) ? W_upd[(128 + k) * 64 + c] : W_edge[k * 64 + c];
        g_W2f[idx] = f2tf32(v);
    }
    for (int idx = t; idx < 64 * NROW; idx += 256) {
        int k = idx / NROW, c = idx % NROW;
        float v = 0.f;
        if (c < 64)        v = W_upd[k * 64 + c];
        else if (c < 128)  v = W_upd[(64 + k) * 64 + (c - 64)];
        else if (c < 192)  v = W_node[k * 64 + (c - 128)];
        else if (c == 192) v = W_attn[k];
        else if (c == 193) v = W_attn[64 + k];
        g_Wn[idx] = v;
    }
    if (t < 64) {
        g_cvec[t] = b_edge[t] + 2.f * b_node[t];
        g_Wa3[t]  = W_attn[128 + t];
    }
    if (t == 0) {
        g_battn = b_attn[0];
        int is64 = 1;
        for (int i = 0; i < 32; i++)
            if (eidx_raw[2 * i + 1] != 0u) { is64 = 0; break; }
        g_idx64 = is64;
    }
}

__global__ __launch_bounds__(256) void k_node(const float* __restrict__ ne, int N)
{
    __shared__ float sX[32 * 64];
    __shared__ float sW[16 * NROW];
    int t = threadIdx.x;
    int n0 = blockIdx.x * 32;

    for (int i = t; i < 32 * 64; i += 256) {
        int n = n0 + (i >> 6);
        sX[i] = (n < N) ? ne[(size_t)n * 64 + (i & 63)] : 0.f;
    }
    int w = t >> 5, lane = t & 31;
    bool p2 = lane < 18;

    float acc[4][8];
    #pragma unroll
    for (int i = 0; i < 4; i++)
        #pragma unroll
        for (int j = 0; j < 8; j++) acc[i][j] = 0.f;

    for (int stage = 0; stage < 4; stage++) {
        __syncthreads();
        for (int i = t; i < 16 * NROW; i += 256) sW[i] = g_Wn[stage * 16 * NROW + i];
        __syncthreads();
        #pragma unroll 4
        for (int kk = 0; kk < 16; kk++) {
            int k = stage * 16 + kk;
            float4 w0 = *(float4*)&sW[kk * NROW + lane * 4];
            float4 w1 = p2 ? *(float4*)&sW[kk * NROW + 128 + lane * 4]
                           : make_float4(0.f, 0.f, 0.f, 0.f);
            #pragma unroll
            for (int i = 0; i < 4; i++) {
                float x = sX[(w * 4 + i) * 64 + k];
                acc[i][0] += x * w0.x; acc[i][1] += x * w0.y; acc[i][2] += x * w0.z; acc[i][3] += x * w0.w;
                acc[i][4] += x * w1.x; acc[i][5] += x * w1.y; acc[i][6] += x * w1.z; acc[i][7] += x * w1.w;
            }
        }
    }
    #pragma unroll
    for (int i = 0; i < 4; i++) {
        int n = n0 + w * 4 + i;
        if (n >= N) continue;
        float* dst = g_node + (size_t)n * NROW;
        *(float4*)&dst[lane * 4] = make_float4(acc[i][0], acc[i][1], acc[i][2], acc[i][3]);
        if (p2)
            *(float4*)&dst[128 + lane * 4] = make_float4(acc[i][4], acc[i][5], acc[i][6], acc[i][7]);
    }
}

// dummy kernel — keeps k_edge in the fixed ncu capture slot
__global__ void k_mark() { if (threadIdx.x < 64) g_Mg[threadIdx.x] = 0.f; }

// smem (floats): sAu[64*68] | sRes[64*68] | sUf[64*64] | sPM[8*68] | sPS[8*68] | misc
#define SA_F  (64 * 68)
#define SUF_F (64 * 64)
#define SP_F  (8 * 68)
#define SMEM_F (2 * SA_F + SUF_F + 2 * SP_F + 256)
#define SMEM_BYTES (SMEM_F * 4)

__global__ __launch_bounds__(256, 4) void k_edge(const float* __restrict__ eemb,
                                                 const void*  __restrict__ eidx,
                                                 const float* __restrict__ bupd,
                                                 float*       __restrict__ out,
                                                 int E)
{
    extern __shared__ float smem[];
    unsigned* sAu   = (unsigned*)smem;       // edge tf32 → updated tf32 → T (fp32 bits)
    float*    sRes  = smem + SA_F;           // E3 → P3s+P3d
    float*    sUf   = smem + 2 * SA_F;       // updated fp32 (pitch 64)
    float*    sPM   = smem + 2 * SA_F + SUF_F;
    float*    sPS   = sPM + SP_F;
    float*    sWa   = sPS + SP_F;
    float*    sGate = sWa + 64;
    int*      sSrc  = (int*)(sGate + 64);    // byte offsets into g_node
    int*      sDst  = sSrc + 64;

    int t = threadIdx.x;
    int e0g = blockIdx.x * 64;
    int idx64 = g_idx64;

    if (t < 128) {
        int j = t & 63;
        int ee = min(e0g + j, E - 1);
        size_t pos = (t < 64) ? (size_t)ee : (size_t)E + (size_t)ee;
        int v = idx64 ? (int)((const long long*)eidx)[pos] : ((const int*)eidx)[pos];
        if (t < 64) sSrc[j] = v * NRB; else sDst[j] = v * NRB;
    }
    if (t >= 128 && t < 192) sWa[t - 128] = g_Wa3[t - 128];
    for (int i = t; i < 64 * 64; i += 256) {
        int e = i >> 6, k = i & 63;
        int ee = min(e0g + e, E - 1);
        sAu[e * 68 + k] = f2tf32(eemb[(size_t)ee * 64 + k]);
    }
    __syncthreads();

    int lane = t & 31, warp = t >> 5;
    int m0 = (warp & 3) * 16;
    int ng = warp >> 2;
    int n0 = ng * 32;
    int g = lane >> 2, q = lane & 3;
    const uint4* Wf = (const uint4*)g_W2f;
    const char* nb = (const char*)g_node;

    // ---- MMA1: E3 = A @ Wu3 ----
    float acc[4][4];
    #pragma unroll
    for (int nt = 0; nt < 4; nt++)
        #pragma unroll
        for (int j = 0; j < 4; j++) acc[nt][j] = 0.f;
    #pragma unroll
    for (int kk = 0; kk < 8; kk++) {
        unsigned a0 = sAu[(m0 + g)     * 68 + kk * 8 + q];
        unsigned a1 = sAu[(m0 + g + 8) * 68 + kk * 8 + q];
        unsigned a2 = sAu[(m0 + g)     * 68 + kk * 8 + q + 4];
        unsigned a3 = sAu[(m0 + g + 8) * 68 + kk * 8 + q + 4];
        int b4 = ng * 512 + kk * 64 + lane;
        uint4 w0 = __ldg(&Wf[b4]);
        uint4 w1 = __ldg(&Wf[b4 + 32]);
        mma_tf32(acc[0], a0, a1, a2, a3, w0.x, w0.y);
        mma_tf32(acc[1], a0, a1, a2, a3, w0.z, w0.w);
        mma_tf32(acc[2], a0, a1, a2, a3, w1.x, w1.y);
        mma_tf32(acc[3], a0, a1, a2, a3, w1.z, w1.w);
    }
    #pragma unroll
    for (int nt = 0; nt < 4; nt++) {
        int col = n0 + nt * 8 + q * 2;
        sRes[(m0 + g)     * 68 + col]     = acc[nt][0];
        sRes[(m0 + g)     * 68 + col + 1] = acc[nt][1];
        sRes[(m0 + g + 8) * 68 + col]     = acc[nt][2];
        sRes[(m0 + g + 8) * 68 + col + 1] = acc[nt][3];
    }
    // gate
    if (t < 64) {
        float s = 0.f;
        #pragma unroll 16
        for (int k = 0; k < 64; k++) s += __uint_as_float(sAu[t * 68 + k]) * sWa[k];
        float a1v = *(const float*)(nb + sSrc[t] + 768);
        float a2v = *(const float*)(nb + sDst[t] + 772);
        sGate[t] = 1.f / (1.f + __expf(-lrelu_f(a1v + a2v + s + g_battn)));
    }
    __syncthreads();

    // ---- Phase B1: ALL gathers (P1,P2,P3s,P3d); updated; P3sum → sRes ----
    int c = lane * 2;
    int cb = c * 4;                 // channel byte offset
    int ebase = warp * 8;
    float2 bu2 = make_float2(bupd[c], bupd[c + 1]);
    float2 cv2 = make_float2(g_cvec[c], g_cvec[c + 1]);

    #pragma unroll
    for (int i0 = 0; i0 < 8; i0 += 2) {
        float2 P1[2], P2[2], P3s[2], P3d[2];
        #pragma unroll
        for (int i = 0; i < 2; i++) {
            int e = ebase + i0 + i;
            const char* ns = nb + sSrc[e];
            const char* nd = nb + sDst[e];
            P1[i]  = *(const float2*)(ns + cb);
            P2[i]  = *(const float2*)(nd + 256 + cb);
            P3s[i] = *(const float2*)(ns + 512 + cb);
            P3d[i] = *(const float2*)(nd + 512 + cb);
        }
        #pragma unroll
        for (int i = 0; i < 2; i++) {
            int e = ebase + i0 + i;
            float gt = sGate[e];
            float2 e3 = *(const float2*)&sRes[e * 68 + c];
            float2 u;
            u.x = gt * (P1[i].x + P2[i].x + e3.x + bu2.x);
            u.y = gt * (P1[i].y + P2[i].y + e3.y + bu2.y);
            *(float2*)&sUf[e * 64 + c] = u;
            uint2 ut = make_uint2(f2tf32(u.x), f2tf32(u.y));
            *(uint2*)&sAu[e * 68 + c] = ut;
            float2 p3 = make_float2(P3s[i].x + P3d[i].x, P3s[i].y + P3d[i].y);
            *(float2*)&sRes[e * 68 + c] = p3;
        }
    }
    __syncthreads();

    // ---- MMA2: T = updated @ W_edge (reads sAu; T stored back into sAu) ----
    #pragma unroll
    for (int nt = 0; nt < 4; nt++)
        #pragma unroll
        for (int j = 0; j < 4; j++) acc[nt][j] = 0.f;
    #pragma unroll
    for (int kk = 0; kk < 8; kk++) {
        unsigned a0 = sAu[(m0 + g)     * 68 + kk * 8 + q];
        unsigned a1 = sAu[(m0 + g + 8) * 68 + kk * 8 + q];
        unsigned a2 = sAu[(m0 + g)     * 68 + kk * 8 + q + 4];
        unsigned a3 = sAu[(m0 + g + 8) * 68 + kk * 8 + q + 4];
        int b4 = 1024 + ng * 512 + kk * 64 + lane;
        uint4 w0 = __ldg(&Wf[b4]);
        uint4 w1 = __ldg(&Wf[b4 + 32]);
        mma_tf32(acc[0], a0, a1, a2, a3, w0.x, w0.y);
        mma_tf32(acc[1], a0, a1, a2, a3, w0.z, w0.w);
        mma_tf32(acc[2], a0, a1, a2, a3, w1.x, w1.y);
        mma_tf32(acc[3], a0, a1, a2, a3, w1.z, w1.w);
    }
    __syncthreads();   // all sAu reads (fragments) complete
    #pragma unroll
    for (int nt = 0; nt < 4; nt++) {
        int col = n0 + nt * 8 + q * 2;
        sAu[(m0 + g)     * 68 + col]     = __float_as_uint(acc[nt][0]);
        sAu[(m0 + g)     * 68 + col + 1] = __float_as_uint(acc[nt][1]);
        sAu[(m0 + g + 8) * 68 + col]     = __float_as_uint(acc[nt][2]);
        sAu[(m0 + g + 8) * 68 + col + 1] = __float_as_uint(acc[nt][3]);
    }
    __syncthreads();

    // ---- Phase B2: pure smem — z = lrelu(T + P3sum + cvec); softmax; store ----
    float2 zs[8];
    #pragma unroll
    for (int i = 0; i < 8; i++) {
        int e = ebase + i;
        bool v = (e0g + e) < E;
        uint2 tb = *(const uint2*)&sAu[e * 68 + c];
        float2 p3 = *(const float2*)&sRes[e * 68 + c];
        float zx = lrelu_f(__uint_as_float(tb.x) + p3.x + cv2.x);
        float zy = lrelu_f(__uint_as_float(tb.y) + p3.y + cv2.y);
        zs[i] = v ? make_float2(zx, zy) : make_float2(-1e30f, -1e30f);
    }
    float2 ml = make_float2(-1e30f, -1e30f);
    #pragma unroll
    for (int i = 0; i < 8; i++) {
        ml.x = fmaxf(ml.x, zs[i].x);
        ml.y = fmaxf(ml.y, zs[i].y);
    }
    *(float2*)&sPM[warp * 68 + c] = ml;
    __syncthreads();
    float2 mb = make_float2(-1e30f, -1e30f);
    #pragma unroll
    for (int w2 = 0; w2 < 8; w2++) {
        mb.x = fmaxf(mb.x, sPM[w2 * 68 + c]);
        mb.y = fmaxf(mb.y, sPM[w2 * 68 + c + 1]);
    }
    float2 sl = make_float2(0.f, 0.f);
    #pragma unroll
    for (int i = 0; i < 8; i++) {
        int e = ebase + i;
        if ((e0g + e) < E) {
            float ex = __expf(zs[i].x - mb.x);
            float ey = __expf(zs[i].y - mb.y);
            sl.x += ex; sl.y += ey;
            float2 u = *(const float2*)&sUf[e * 64 + c];
            float2 o = make_float2(u.x * ex, u.y * ey);
            *(float2*)&out[(size_t)(e0g + e) * 64 + c] = o;
        }
    }
    *(float2*)&sPS[warp * 68 + c] = sl;
    __syncthreads();
    if (warp == 0) {
        float sx = 0.f, sy = 0.f;
        #pragma unroll
        for (int w2 = 0; w2 < 8; w2++) {
            sx += sPS[w2 * 68 + c];
            sy += sPS[w2 * 68 + c + 1];
        }
        g_partM[c * MAXNB + blockIdx.x]       = mb.x;
        g_partM[(c + 1) * MAXNB + blockIdx.x] = mb.y;
        g_partS[c * MAXNB + blockIdx.x]       = sx;
        g_partS[(c + 1) * MAXNB + blockIdx.x] = sy;
    }
}

__global__ void k_combine(int NB)
{
    int c = blockIdx.x, t = threadIdx.x;
    float m = -1e30f, s = 0.f;
    for (int b = t; b < NB; b += 256) {
        float mb = g_partM[c * MAXNB + b], sb = g_partS[c * MAXNB + b];
        float M2 = fmaxf(m, mb);
        s = s * __expf(m - M2) + sb * __expf(mb - M2);
        m = M2;
    }
    __shared__ float sm[256], ss[256];
    sm[t] = m; ss[t] = s; __syncthreads();
    for (int off = 128; off > 0; off >>= 1) {
        if (t < off) {
            float M2 = fmaxf(sm[t], sm[t + off]);
            ss[t] = ss[t] * __expf(sm[t] - M2) + ss[t + off] * __expf(sm[t + off] - M2);
            sm[t] = M2;
        }
        __syncthreads();
    }
    if (t == 0) { g_Mg[c] = sm[0]; g_invS[c] = 1.f / ss[0]; }
}

__global__ void k_pass2(float4* __restrict__ out, int total4)
{
    int i = blockIdx.x * 256 + threadIdx.x;
    if (i >= total4) return;
    int c0 = (i * 4) & 63;
    int b  = i >> 10;
    float4 o = out[i];
    o.x *= __expf(g_partM[(c0 + 0) * MAXNB + b] - g_Mg[c0 + 0]) * g_invS[c0 + 0];
    o.y *= __expf(g_partM[(c0 + 1) * MAXNB + b] - g_Mg[c0 + 1]) * g_invS[c0 + 1];
    o.z *= __expf(g_partM[(c0 + 2) * MAXNB + b] - g_Mg[c0 + 2]) * g_invS[c0 + 2];
    o.w *= __expf(g_partM[(c0 + 3) * MAXNB + b] - g_Mg[c0 + 3]) * g_invS[c0 + 3];
    out[i] = o;
}

extern "C" void kernel_launch(void* const* d_in, const int* in_sizes, int n_in,
                              void* d_out, int out_size)
{
    const float* eemb = (const float*)d_in[0];
    const float* ne   = (const float*)d_in[2];
    const float* Wa   = (const float*)d_in[3];
    const float* ba   = (const float*)d_in[4];
    const float* Wu   = (const float*)d_in[5];
    const float* bu   = (const float*)d_in[6];
    const float* We   = (const float*)d_in[7];
    const float* be   = (const float*)d_in[8];
    const float* Wn   = (const float*)d_in[9];
    const float* bn   = (const float*)d_in[10];
    const void*  eidx = d_in[11];
    float* out = (float*)d_out;

    int E = in_sizes[0] / 64;
    int N = in_sizes[2] / 64;
    int NB = (E + 63) / 64;

    cudaFuncSetAttribute(k_edge, cudaFuncAttributeMaxDynamicSharedMemorySize, SMEM_BYTES);

    k_prep<<<1, 256>>>(Wa, ba, Wu, bu, We, be, Wn, bn, (const unsigned*)eidx);
    k_node<<<(N + 31) / 32, 256>>>(ne, N);
    k_mark<<<1, 64>>>();
    k_edge<<<NB, 256, SMEM_BYTES>>>(eemb, eidx, bu, out, E);
    k_combine<<<64, 256>>>(NB);
    int total4 = E * 16;
    k_pass2<<<(total4 + 255) / 256, 256>>>((float4*)out, total4);
}

// round 9
// speedup vs baseline: 1.3864x; 1.0913x over previous
#include <cuda_runtime.h>
#include <cuda_fp16.h>

#define SLOPE 0.2f
#define NRB   512                  // node row bytes: P1 h[64] | P2 h[64] | P3 h[64] | a1 f | a2 f | pad
#define NWROW 200                  // g_Wn columns
#define MAXN  100352
#define MAXE  1000192
#define MAXNB (MAXE / 64)

__device__ float4   g_node[(size_t)MAXN * (NRB / 16)];   // 51MB, 512B/node
__device__ float    g_partM[64 * MAXNB];
__device__ float    g_partS[64 * MAXNB];
__device__ unsigned g_W2f[8192];   // tf32, fragment-major: [ph][ng][kk][half][lane][4]
__device__ float    g_Wn[64 * NWROW];
__device__ float    g_Wa3[64];
__device__ float    g_cvec[64];
__device__ float    g_Mg[64];
__device__ float    g_invS[64];
__device__ float    g_battn;
__device__ int      g_idx64;

__device__ __forceinline__ float lrelu_f(float x) { return x >= 0.f ? x : SLOPE * x; }
__device__ __forceinline__ unsigned f2tf32(float f) {
    unsigned u; asm("cvt.rna.tf32.f32 %0, %1;" : "=r"(u) : "f"(f)); return u;
}
__device__ __forceinline__ void mma_tf32(float* c, unsigned a0, unsigned a1, unsigned a2, unsigned a3,
                                         unsigned b0, unsigned b1) {
    asm volatile("mma.sync.aligned.m16n8k8.row.col.f32.tf32.tf32.f32 "
                 "{%0,%1,%2,%3}, {%4,%5,%6,%7}, {%8,%9}, {%0,%1,%2,%3};"
                 : "+f"(c[0]), "+f"(c[1]), "+f"(c[2]), "+f"(c[3])
                 : "r"(a0), "r"(a1), "r"(a2), "r"(a3), "r"(b0), "r"(b1));
}

__global__ void k_prep(const float* __restrict__ W_attn, const float* __restrict__ b_attn,
                       const float* __restrict__ W_upd,  const float* __restrict__ b_upd,
                       const float* __restrict__ W_edge, const float* __restrict__ b_edge,
                       const float* __restrict__ W_node, const float* __restrict__ b_node,
                       const unsigned* __restrict__ eidx_raw)
{
    int t = threadIdx.x;
    for (int idx = t; idx < 8192; idx += 256) {
        int j    = idx & 3;
        int lane = (idx >> 2) & 31;
        int half = (idx >> 7) & 1;
        int kk   = (idx >> 8) & 7;
        int ng   = (idx >> 11) & 1;
        int ph   = (idx >> 12) & 1;
        int g = lane >> 2, q = lane & 3;
        int nt = half * 2 + (j >> 1), b = j & 1;
        int k = kk * 8 + q + b * 4;
        int c = ng * 32 + nt * 8 + g;
        float v = (ph == 0) ? W_upd[(128 + k) * 64 + c] : W_edge[k * 64 + c];
        g_W2f[idx] = f2tf32(v);
    }
    for (int idx = t; idx < 64 * NWROW; idx += 256) {
        int k = idx / NWROW, c = idx % NWROW;
        float v = 0.f;
        if (c < 64)        v = W_upd[k * 64 + c];
        else if (c < 128)  v = W_upd[(64 + k) * 64 + (c - 64)];
        else if (c < 192)  v = W_node[k * 64 + (c - 128)];
        else if (c == 192) v = W_attn[k];
        else if (c == 193) v = W_attn[64 + k];
        g_Wn[idx] = v;
    }
    if (t < 64) {
        g_cvec[t] = b_edge[t] + 2.f * b_node[t];
        g_Wa3[t]  = W_attn[128 + t];
    }
    if (t == 0) {
        g_battn = b_attn[0];
        int is64 = 1;
        for (int i = 0; i < 32; i++)
            if (eidx_raw[2 * i + 1] != 0u) { is64 = 0; break; }
        g_idx64 = is64;
    }
}

__global__ __launch_bounds__(256) void k_node(const float* __restrict__ ne, int N)
{
    __shared__ float sX[32 * 64];
    __shared__ float sW[16 * NWROW];
    int t = threadIdx.x;
    int n0 = blockIdx.x * 32;

    for (int i = t; i < 32 * 64; i += 256) {
        int n = n0 + (i >> 6);
        sX[i] = (n < N) ? ne[(size_t)n * 64 + (i & 63)] : 0.f;
    }
    int w = t >> 5, lane = t & 31;
    bool p2 = lane < 18;

    float acc[4][8];
    #pragma unroll
    for (int i = 0; i < 4; i++)
        #pragma unroll
        for (int j = 0; j < 8; j++) acc[i][j] = 0.f;

    for (int stage = 0; stage < 4; stage++) {
        __syncthreads();
        for (int i = t; i < 16 * NWROW; i += 256) sW[i] = g_Wn[stage * 16 * NWROW + i];
        __syncthreads();
        #pragma unroll 4
        for (int kk = 0; kk < 16; kk++) {
            int k = stage * 16 + kk;
            float4 w0 = *(float4*)&sW[kk * NWROW + lane * 4];
            float4 w1 = p2 ? *(float4*)&sW[kk * NWROW + 128 + lane * 4]
                           : make_float4(0.f, 0.f, 0.f, 0.f);
            #pragma unroll
            for (int i = 0; i < 4; i++) {
                float x = sX[(w * 4 + i) * 64 + k];
                acc[i][0] += x * w0.x; acc[i][1] += x * w0.y; acc[i][2] += x * w0.z; acc[i][3] += x * w0.w;
                acc[i][4] += x * w1.x; acc[i][5] += x * w1.y; acc[i][6] += x * w1.z; acc[i][7] += x * w1.w;
            }
        }
    }
    #pragma unroll
    for (int i = 0; i < 4; i++) {
        int n = n0 + w * 4 + i;
        if (n >= N) continue;
        char* dst = (char*)g_node + (size_t)n * NRB;
        // P1|P2 halves: cols lane*4..+3 → bytes lane*8
        __half2* d0 = (__half2*)(dst + lane * 8);
        d0[0] = __floats2half2_rn(acc[i][0], acc[i][1]);
        d0[1] = __floats2half2_rn(acc[i][2], acc[i][3]);
        if (lane < 16) {          // P3 halves: cols 128+lane*4 → bytes 256+lane*8
            __half2* d1 = (__half2*)(dst + 256 + lane * 8);
            d1[0] = __floats2half2_rn(acc[i][4], acc[i][5]);
            d1[1] = __floats2half2_rn(acc[i][6], acc[i][7]);
        } else if (lane == 16) {  // a1, a2 fp32
            *(float*)(dst + 384) = acc[i][4];
            *(float*)(dst + 388) = acc[i][5];
        }
    }
}

// dummy kernel — keeps k_edge in the fixed ncu capture slot
__global__ void k_mark() { if (threadIdx.x < 64) g_Mg[threadIdx.x] = 0.f; }

// smem (floats): sAu[64*68] | sRes[64*68] | sUf[64*64] | sPM[8*68] | sPS[8*68] | misc
#define SA_F  (64 * 68)
#define SUF_F (64 * 64)
#define SP_F  (8 * 68)
#define SMEM_F (2 * SA_F + SUF_F + 2 * SP_F + 256)
#define SMEM_BYTES (SMEM_F * 4)

__global__ __launch_bounds__(256, 4) void k_edge(const float* __restrict__ eemb,
                                                 const void*  __restrict__ eidx,
                                                 const float* __restrict__ bupd,
                                                 float*       __restrict__ out,
                                                 int E)
{
    extern __shared__ float smem[];
    unsigned* sAu   = (unsigned*)smem;       // edge tf32 → updated tf32 → T (fp32 bits)
    float*    sRes  = smem + SA_F;           // E3 → P3s+P3d
    float*    sUf   = smem + 2 * SA_F;       // updated fp32 (pitch 64)
    float*    sPM   = smem + 2 * SA_F + SUF_F;
    float*    sPS   = sPM + SP_F;
    float*    sWa   = sPS + SP_F;
    float*    sGate = sWa + 64;
    int*      sSrc  = (int*)(sGate + 64);    // byte offsets into g_node
    int*      sDst  = sSrc + 64;

    int t = threadIdx.x;
    int e0g = blockIdx.x * 64;
    int idx64 = g_idx64;

    if (t < 128) {
        int j = t & 63;
        int ee = min(e0g + j, E - 1);
        size_t pos = (t < 64) ? (size_t)ee : (size_t)E + (size_t)ee;
        int v = idx64 ? (int)((const long long*)eidx)[pos] : ((const int*)eidx)[pos];
        if (t < 64) sSrc[j] = v * NRB; else sDst[j] = v * NRB;
    }
    if (t >= 128 && t < 192) sWa[t - 128] = g_Wa3[t - 128];
    for (int i = t; i < 64 * 64; i += 256) {
        int e = i >> 6, k = i & 63;
        int ee = min(e0g + e, E - 1);
        sAu[e * 68 + k] = f2tf32(eemb[(size_t)ee * 64 + k]);
    }
    __syncthreads();

    int lane = t & 31, warp = t >> 5;
    int m0 = (warp & 3) * 16;
    int ng = warp >> 2;
    int n0 = ng * 32;
    int g = lane >> 2, q = lane & 3;
    const uint4* Wf = (const uint4*)g_W2f;
    const char* nb = (const char*)g_node;

    // ---- MMA1: E3 = A @ Wu3 ----
    float acc[4][4];
    #pragma unroll
    for (int nt = 0; nt < 4; nt++)
        #pragma unroll
        for (int j = 0; j < 4; j++) acc[nt][j] = 0.f;
    #pragma unroll
    for (int kk = 0; kk < 8; kk++) {
        unsigned a0 = sAu[(m0 + g)     * 68 + kk * 8 + q];
        unsigned a1 = sAu[(m0 + g + 8) * 68 + kk * 8 + q];
        unsigned a2 = sAu[(m0 + g)     * 68 + kk * 8 + q + 4];
        unsigned a3 = sAu[(m0 + g + 8) * 68 + kk * 8 + q + 4];
        int b4 = ng * 512 + kk * 64 + lane;
        uint4 w0 = __ldg(&Wf[b4]);
        uint4 w1 = __ldg(&Wf[b4 + 32]);
        mma_tf32(acc[0], a0, a1, a2, a3, w0.x, w0.y);
        mma_tf32(acc[1], a0, a1, a2, a3, w0.z, w0.w);
        mma_tf32(acc[2], a0, a1, a2, a3, w1.x, w1.y);
        mma_tf32(acc[3], a0, a1, a2, a3, w1.z, w1.w);
    }
    #pragma unroll
    for (int nt = 0; nt < 4; nt++) {
        int col = n0 + nt * 8 + q * 2;
        sRes[(m0 + g)     * 68 + col]     = acc[nt][0];
        sRes[(m0 + g)     * 68 + col + 1] = acc[nt][1];
        sRes[(m0 + g + 8) * 68 + col]     = acc[nt][2];
        sRes[(m0 + g + 8) * 68 + col + 1] = acc[nt][3];
    }
    // gate
    if (t < 64) {
        float s = 0.f;
        #pragma unroll 16
        for (int k = 0; k < 64; k++) s += __uint_as_float(sAu[t * 68 + k]) * sWa[k];
        float a1v = *(const float*)(nb + sSrc[t] + 384);
        float a2v = *(const float*)(nb + sDst[t] + 388);
        sGate[t] = 1.f / (1.f + __expf(-lrelu_f(a1v + a2v + s + g_battn)));
    }
    __syncthreads();

    // ---- Phase B1: ALL gathers (half2); updated; P3sum → sRes ----
    int c = lane * 2;
    int cb = lane * 4;              // half2 byte offset for channels 2l,2l+1
    int ebase = warp * 8;
    float2 bu2 = make_float2(bupd[c], bupd[c + 1]);
    float2 cv2 = make_float2(g_cvec[c], g_cvec[c + 1]);

    #pragma unroll
    for (int i0 = 0; i0 < 8; i0 += 4) {
        __half2 H1[4], H2[4], H3s[4], H3d[4];
        #pragma unroll
        for (int i = 0; i < 4; i++) {
            int e = ebase + i0 + i;
            const char* ns = nb + sSrc[e];
            const char* nd = nb + sDst[e];
            H1[i]  = *(const __half2*)(ns + cb);
            H2[i]  = *(const __half2*)(nd + 128 + cb);
            H3s[i] = *(const __half2*)(ns + 256 + cb);
            H3d[i] = *(const __half2*)(nd + 256 + cb);
        }
        #pragma unroll
        for (int i = 0; i < 4; i++) {
            int e = ebase + i0 + i;
            float gt = sGate[e];
            float2 p1 = __half22float2(H1[i]);
            float2 p2 = __half22float2(H2[i]);
            float2 p3a = __half22float2(H3s[i]);
            float2 p3b = __half22float2(H3d[i]);
            float2 e3 = *(const float2*)&sRes[e * 68 + c];
            float2 u;
            u.x = gt * (p1.x + p2.x + e3.x + bu2.x);
            u.y = gt * (p1.y + p2.y + e3.y + bu2.y);
            *(float2*)&sUf[e * 64 + c] = u;
            uint2 ut = make_uint2(f2tf32(u.x), f2tf32(u.y));
            *(uint2*)&sAu[e * 68 + c] = ut;
            *(float2*)&sRes[e * 68 + c] = make_float2(p3a.x + p3b.x, p3a.y + p3b.y);
        }
    }
    __syncthreads();

    // ---- MMA2: T = updated @ W_edge (reads sAu; T stored back into sAu) ----
    #pragma unroll
    for (int nt = 0; nt < 4; nt++)
        #pragma unroll
        for (int j = 0; j < 4; j++) acc[nt][j] = 0.f;
    #pragma unroll
    for (int kk = 0; kk < 8; kk++) {
        unsigned a0 = sAu[(m0 + g)     * 68 + kk * 8 + q];
        unsigned a1 = sAu[(m0 + g + 8) * 68 + kk * 8 + q];
        unsigned a2 = sAu[(m0 + g)     * 68 + kk * 8 + q + 4];
        unsigned a3 = sAu[(m0 + g + 8) * 68 + kk * 8 + q + 4];
        int b4 = 1024 + ng * 512 + kk * 64 + lane;
        uint4 w0 = __ldg(&Wf[b4]);
        uint4 w1 = __ldg(&Wf[b4 + 32]);
        mma_tf32(acc[0], a0, a1, a2, a3, w0.x, w0.y);
        mma_tf32(acc[1], a0, a1, a2, a3, w0.z, w0.w);
        mma_tf32(acc[2], a0, a1, a2, a3, w1.x, w1.y);
        mma_tf32(acc[3], a0, a1, a2, a3, w1.z, w1.w);
    }
    __syncthreads();   // all sAu fragment reads complete
    #pragma unroll
    for (int nt = 0; nt < 4; nt++) {
        int col = n0 + nt * 8 + q * 2;
        sAu[(m0 + g)     * 68 + col]     = __float_as_uint(acc[nt][0]);
        sAu[(m0 + g)     * 68 + col + 1] = __float_as_uint(acc[nt][1]);
        sAu[(m0 + g + 8) * 68 + col]     = __float_as_uint(acc[nt][2]);
        sAu[(m0 + g + 8) * 68 + col + 1] = __float_as_uint(acc[nt][3]);
    }
    __syncthreads();

    // ---- Phase B2: pure smem — z = lrelu(T + P3sum + cvec); softmax; store ----
    float2 zs[8];
    #pragma unroll
    for (int i = 0; i < 8; i++) {
        int e = ebase + i;
        bool v = (e0g + e) < E;
        uint2 tb = *(const uint2*)&sAu[e * 68 + c];
        float2 p3 = *(const float2*)&sRes[e * 68 + c];
        float zx = lrelu_f(__uint_as_float(tb.x) + p3.x + cv2.x);
        float zy = lrelu_f(__uint_as_float(tb.y) + p3.y + cv2.y);
        zs[i] = v ? make_float2(zx, zy) : make_float2(-1e30f, -1e30f);
    }
    float2 ml = make_float2(-1e30f, -1e30f);
    #pragma unroll
    for (int i = 0; i < 8; i++) {
        ml.x = fmaxf(ml.x, zs[i].x);
        ml.y = fmaxf(ml.y, zs[i].y);
    }
    *(float2*)&sPM[warp * 68 + c] = ml;
    __syncthreads();
    float2 mb = make_float2(-1e30f, -1e30f);
    #pragma unroll
    for (int w2 = 0; w2 < 8; w2++) {
        mb.x = fmaxf(mb.x, sPM[w2 * 68 + c]);
        mb.y = fmaxf(mb.y, sPM[w2 * 68 + c + 1]);
    }
    float2 sl = make_float2(0.f, 0.f);
    #pragma unroll
    for (int i = 0; i < 8; i++) {
        int e = ebase + i;
        if ((e0g + e) < E) {
            float ex = __expf(zs[i].x - mb.x);
            float ey = __expf(zs[i].y - mb.y);
            sl.x += ex; sl.y += ey;
            float2 u = *(const float2*)&sUf[e * 64 + c];
            float2 o = make_float2(u.x * ex, u.y * ey);
            *(float2*)&out[(size_t)(e0g + e) * 64 + c] = o;
        }
    }
    *(float2*)&sPS[warp * 68 + c] = sl;
    __syncthreads();
    if (warp == 0) {
        float sx = 0.f, sy = 0.f;
        #pragma unroll
        for (int w2 = 0; w2 < 8; w2++) {
            sx += sPS[w2 * 68 + c];
            sy += sPS[w2 * 68 + c + 1];
        }
        g_partM[c * MAXNB + blockIdx.x]       = mb.x;
        g_partM[(c + 1) * MAXNB + blockIdx.x] = mb.y;
        g_partS[c * MAXNB + blockIdx.x]       = sx;
        g_partS[(c + 1) * MAXNB + blockIdx.x] = sy;
    }
}

__global__ void k_combine(int NB)
{
    int c = blockIdx.x, t = threadIdx.x;
    float m = -1e30f, s = 0.f;
    for (int b = t; b < NB; b += 256) {
        float mb = g_partM[c * MAXNB + b], sb = g_partS[c * MAXNB + b];
        float M2 = fmaxf(m, mb);
        s = s * __expf(m - M2) + sb * __expf(mb - M2);
        m = M2;
    }
    __shared__ float sm[256], ss[256];
    sm[t] = m; ss[t] = s; __syncthreads();
    for (int off = 128; off > 0; off >>= 1) {
        if (t < off) {
            float M2 = fmaxf(sm[t], sm[t + off]);
            ss[t] = ss[t] * __expf(sm[t] - M2) + ss[t + off] * __expf(sm[t + off] - M2);
            sm[t] = M2;
        }
        __syncthreads();
    }
    if (t == 0) { g_Mg[c] = sm[0]; g_invS[c] = 1.f / ss[0]; }
}

__global__ void k_pass2(float4* __restrict__ out, int total4)
{
    int i = blockIdx.x * 256 + threadIdx.x;
    if (i >= total4) return;
    int c0 = (i * 4) & 63;
    int b  = i >> 10;
    float4 o = out[i];
    o.x *= __expf(g_partM[(c0 + 0) * MAXNB + b] - g_Mg[c0 + 0]) * g_invS[c0 + 0];
    o.y *= __expf(g_partM[(c0 + 1) * MAXNB + b] - g_Mg[c0 + 1]) * g_invS[c0 + 1];
    o.z *= __expf(g_partM[(c0 + 2) * MAXNB + b] - g_Mg[c0 + 2]) * g_invS[c0 + 2];
    o.w *= __expf(g_partM[(c0 + 3) * MAXNB + b] - g_Mg[c0 + 3]) * g_invS[c0 + 3];
    out[i] = o;
}

extern "C" void kernel_launch(void* const* d_in, const int* in_sizes, int n_in,
                              void* d_out, int out_size)
{
    const float* eemb = (const float*)d_in[0];
    const float* ne   = (const float*)d_in[2];
    const float* Wa   = (const float*)d_in[3];
    const float* ba   = (const float*)d_in[4];
    const float* Wu   = (const float*)d_in[5];
    const float* bu   = (const float*)d_in[6];
    const float* We   = (const float*)d_in[7];
    const float* be   = (const float*)d_in[8];
    const float* Wn   = (const float*)d_in[9];
    const float* bn   = (const float*)d_in[10];
    const void*  eidx = d_in[11];
    float* out = (float*)d_out;

    int E = in_sizes[0] / 64;
    int N = in_sizes[2] / 64;
    int NB = (E + 63) / 64;

    cudaFuncSetAttribute(k_edge, cudaFuncAttributeMaxDynamicSharedMemorySize, SMEM_BYTES);

    k_prep<<<1, 256>>>(Wa, ba, Wu, bu, We, be, Wn, bn, (const unsigned*)eidx);
    k_node<<<(N + 31) / 32, 256>>>(ne, N);
    k_mark<<<1, 64>>>();
    k_edge<<<NB, 256, SMEM_BYTES>>>(eemb, eidx, bu, out, E);
    k_combine<<<64, 256>>>(NB);
    int total4 = E * 16;
    k_pass2<<<(total4 + 255) / 256, 256>>>((float4*)out, total4);
}

// round 10
// speedup vs baseline: 1.4269x; 1.0292x over previous
#include <cuda_runtime.h>
#include <cuda_fp16.h>

#define SLOPE 0.2f
#define NRB   512                  // node row bytes: P1 h[64] | P2 h[64] | P3 h[64] | a1 f | a2 f | pad
#define MAXN  100352
#define MAXE  1000192
#define MAXNB (MAXE / 64)

__device__ float4   g_node[(size_t)MAXN * (NRB / 16)];   // 51MB, 512B/node
__device__ float    g_partM[64 * MAXNB];
__device__ float    g_partS[64 * MAXNB];
__device__ unsigned g_W2f[8192];    // k_edge weights, fragment-major
__device__ unsigned g_Wnf[16384];   // k_node weights, fragment-major [ng(4)][kk(8)][lane(32)][16]
__device__ float    g_Wa3[64];
__device__ float    g_cvec[64];
__device__ float    g_Mg[64];
__device__ float    g_invS[64];
__device__ float    g_battn;
__device__ int      g_idx64;

__device__ __forceinline__ float lrelu_f(float x) { return x >= 0.f ? x : SLOPE * x; }
__device__ __forceinline__ unsigned f2tf32(float f) {
    unsigned u; asm("cvt.rna.tf32.f32 %0, %1;" : "=r"(u) : "f"(f)); return u;
}
__device__ __forceinline__ void mma_tf32(float* c, unsigned a0, unsigned a1, unsigned a2, unsigned a3,
                                         unsigned b0, unsigned b1) {
    asm volatile("mma.sync.aligned.m16n8k8.row.col.f32.tf32.tf32.f32 "
                 "{%0,%1,%2,%3}, {%4,%5,%6,%7}, {%8,%9}, {%0,%1,%2,%3};"
                 : "+f"(c[0]), "+f"(c[1]), "+f"(c[2]), "+f"(c[3])
                 : "r"(a0), "r"(a1), "r"(a2), "r"(a3), "r"(b0), "r"(b1));
}

// node-precompute weight value for (k, col): cols 0-63 P1, 64-127 P2, 128-191 P3, 192 a1, 193 a2
__device__ __forceinline__ float wn_val(int k, int col,
                                        const float* W_upd, const float* W_node, const float* W_attn)
{
    if (col < 64)   return W_upd[k * 64 + col];
    if (col < 128)  return W_upd[(64 + k) * 64 + (col - 64)];
    if (col < 192)  return W_node[k * 64 + (col - 128)];
    if (col == 192) return W_attn[k];
    if (col == 193) return W_attn[64 + k];
    return 0.f;
}

__global__ void k_prep(const float* __restrict__ W_attn, const float* __restrict__ b_attn,
                       const float* __restrict__ W_upd,  const float* __restrict__ b_upd,
                       const float* __restrict__ W_edge, const float* __restrict__ b_edge,
                       const float* __restrict__ W_node, const float* __restrict__ b_node,
                       const unsigned* __restrict__ eidx_raw)
{
    int t = threadIdx.x;
    for (int idx = t; idx < 8192; idx += 256) {
        int j    = idx & 3;
        int lane = (idx >> 2) & 31;
        int half = (idx >> 7) & 1;
        int kk   = (idx >> 8) & 7;
        int ng   = (idx >> 11) & 1;
        int ph   = (idx >> 12) & 1;
        int g = lane >> 2, q = lane & 3;
        int nt = half * 2 + (j >> 1), b = j & 1;
        int k = kk * 8 + q + b * 4;
        int c = ng * 32 + nt * 8 + g;
        float v = (ph == 0) ? W_upd[(128 + k) * 64 + c] : W_edge[k * 64 + c];
        g_W2f[idx] = f2tf32(v);
    }
    for (int idx = t; idx < 16384; idx += 256) {
        int j    = idx & 15;
        int lane = (idx >> 4) & 31;
        int kk   = (idx >> 9) & 7;
        int ng   = (idx >> 12) & 3;
        float v = 0.f;
        if (j < 14) {
            int g = lane >> 2, q = lane & 3;
            int nt = j >> 1, b = j & 1;
            int k = kk * 8 + q + b * 4;
            int col = ng * 56 + nt * 8 + g;
            v = wn_val(k, col, W_upd, W_node, W_attn);
        }
        g_Wnf[idx] = f2tf32(v);
    }
    if (t < 64) {
        g_cvec[t] = b_edge[t] + 2.f * b_node[t];
        g_Wa3[t]  = W_attn[128 + t];
    }
    if (t == 0) {
        g_battn = b_attn[0];
        int is64 = 1;
        for (int i = 0; i < 32; i++)
            if (eidx_raw[2 * i + 1] != 0u) { is64 = 0; break; }
        g_idx64 = is64;
    }
}

// tf32 MMA node precompute: 32 nodes/block, N=224 padded cols (194 used), K=64
__global__ __launch_bounds__(256) void k_node(const float* __restrict__ ne, int N)
{
    __shared__ unsigned sX[32 * 68];
    __shared__ float    sOut[32 * 228];
    int t = threadIdx.x;
    int n0 = blockIdx.x * 32;

    for (int i = t; i < 32 * 64; i += 256) {
        int n = n0 + (i >> 6);
        float v = (n < N) ? ne[(size_t)n * 64 + (i & 63)] : 0.f;
        sX[(i >> 6) * 68 + (i & 63)] = f2tf32(v);
    }
    __syncthreads();

    int lane = t & 31, warp = t >> 5;
    int m0 = (warp & 1) * 16;     // 2 m-groups of 16 nodes
    int ng = warp >> 1;           // 4 n-groups of 56 cols
    int n0c = ng * 56;
    int g = lane >> 2, q = lane & 3;
    const uint4* W4 = (const uint4*)g_Wnf;
    const uint2* W2 = (const uint2*)g_Wnf;

    float acc[7][4];
    #pragma unroll
    for (int nt = 0; nt < 7; nt++)
        #pragma unroll
        for (int j = 0; j < 4; j++) acc[nt][j] = 0.f;

    #pragma unroll
    for (int kk = 0; kk < 8; kk++) {
        unsigned a0 = sX[(m0 + g)     * 68 + kk * 8 + q];
        unsigned a1 = sX[(m0 + g + 8) * 68 + kk * 8 + q];
        unsigned a2 = sX[(m0 + g)     * 68 + kk * 8 + q + 4];
        unsigned a3 = sX[(m0 + g + 8) * 68 + kk * 8 + q + 4];
        int base = ((ng * 8 + kk) * 32 + lane);          // ×16 unsigneds
        uint4 w0 = __ldg(&W4[base * 4]);
        uint4 w1 = __ldg(&W4[base * 4 + 1]);
        uint4 w2 = __ldg(&W4[base * 4 + 2]);
        uint2 w3 = __ldg(&W2[base * 8 + 6]);
        mma_tf32(acc[0], a0, a1, a2, a3, w0.x, w0.y);
        mma_tf32(acc[1], a0, a1, a2, a3, w0.z, w0.w);
        mma_tf32(acc[2], a0, a1, a2, a3, w1.x, w1.y);
        mma_tf32(acc[3], a0, a1, a2, a3, w1.z, w1.w);
        mma_tf32(acc[4], a0, a1, a2, a3, w2.x, w2.y);
        mma_tf32(acc[5], a0, a1, a2, a3, w2.z, w2.w);
        mma_tf32(acc[6], a0, a1, a2, a3, w3.x, w3.y);
    }
    #pragma unroll
    for (int nt = 0; nt < 7; nt++) {
        int col = n0c + nt * 8 + q * 2;
        sOut[(m0 + g)     * 228 + col]     = acc[nt][0];
        sOut[(m0 + g)     * 228 + col + 1] = acc[nt][1];
        sOut[(m0 + g + 8) * 228 + col]     = acc[nt][2];
        sOut[(m0 + g + 8) * 228 + col + 1] = acc[nt][3];
    }
    __syncthreads();

    // pack to fp16 node table
    for (int i = t; i < 32 * 64; i += 256) {
        int n = i >> 6, j = i & 63;
        if (n0 + n >= N) continue;
        char* dst = (char*)g_node + (size_t)(n0 + n) * NRB;
        *(__half2*)(dst + j * 4) = __floats2half2_rn(sOut[n * 228 + 2 * j], sOut[n * 228 + 2 * j + 1]);
    }
    for (int i = t; i < 32 * 32; i += 256) {
        int n = i >> 5, j = i & 31;
        if (n0 + n >= N) continue;
        char* dst = (char*)g_node + (size_t)(n0 + n) * NRB;
        *(__half2*)(dst + 256 + j * 4) = __floats2half2_rn(sOut[n * 228 + 128 + 2 * j], sOut[n * 228 + 129 + 2 * j]);
    }
    if (t < 32 && n0 + t < N) {
        char* dst = (char*)g_node + (size_t)(n0 + t) * NRB;
        *(float*)(dst + 384) = sOut[t * 228 + 192];
        *(float*)(dst + 388) = sOut[t * 228 + 193];
    }
}

// dummy kernel — keeps k_edge in the fixed ncu capture slot
__global__ void k_mark() { if (threadIdx.x < 64) g_Mg[threadIdx.x] = 0.f; }

// smem (floats): sAu[64*68] | sRes[64*68] | sUf[64*64] | sPM[8*68] | sPS[8*68] | misc
#define SA_F  (64 * 68)
#define SUF_F (64 * 64)
#define SP_F  (8 * 68)
#define SMEM_F (2 * SA_F + SUF_F + 2 * SP_F + 256)
#define SMEM_BYTES (SMEM_F * 4)

__global__ __launch_bounds__(256, 4) void k_edge(const float* __restrict__ eemb,
                                                 const void*  __restrict__ eidx,
                                                 const float* __restrict__ bupd,
                                                 float*       __restrict__ out,
                                                 int E)
{
    extern __shared__ float smem[];
    unsigned* sAu   = (unsigned*)smem;       // edge tf32 → updated tf32 → T (fp32 bits)
    float*    sRes  = smem + SA_F;           // E3 → P3s+P3d
    float*    sUf   = smem + 2 * SA_F;       // updated fp32 (pitch 64)
    float*    sPM   = smem + 2 * SA_F + SUF_F;
    float*    sPS   = sPM + SP_F;
    float*    sWa   = sPS + SP_F;
    float*    sGate = sWa + 64;
    int*      sSrc  = (int*)(sGate + 64);    // byte offsets into g_node
    int*      sDst  = sSrc + 64;

    int t = threadIdx.x;
    int e0g = blockIdx.x * 64;
    int idx64 = g_idx64;

    if (t < 128) {
        int j = t & 63;
        int ee = min(e0g + j, E - 1);
        size_t pos = (t < 64) ? (size_t)ee : (size_t)E + (size_t)ee;
        int v = idx64 ? (int)((const long long*)eidx)[pos] : ((const int*)eidx)[pos];
        if (t < 64) sSrc[j] = v * NRB; else sDst[j] = v * NRB;
    }
    if (t >= 128 && t < 192) sWa[t - 128] = g_Wa3[t - 128];
    for (int i = t; i < 64 * 64; i += 256) {
        int e = i >> 6, k = i & 63;
        int ee = min(e0g + e, E - 1);
        sAu[e * 68 + k] = f2tf32(eemb[(size_t)ee * 64 + k]);
    }
    __syncthreads();

    int lane = t & 31, warp = t >> 5;
    int m0 = (warp & 3) * 16;
    int ng = warp >> 2;
    int n0 = ng * 32;
    int g = lane >> 2, q = lane & 3;
    const uint4* Wf = (const uint4*)g_W2f;
    const char* nb = (const char*)g_node;

    int c = lane * 2;
    int cb = lane * 4;
    int ebase = warp * 8;

    // ---- prefetch gathers for edges ebase..ebase+3 (overlap with MMA1) ----
    __half2 H1[4], H2[4], H3s[4], H3d[4];
    #pragma unroll
    for (int i = 0; i < 4; i++) {
        int e = ebase + i;
        const char* ns = nb + sSrc[e];
        const char* nd = nb + sDst[e];
        H1[i]  = *(const __half2*)(ns + cb);
        H2[i]  = *(const __half2*)(nd + 128 + cb);
        H3s[i] = *(const __half2*)(ns + 256 + cb);
        H3d[i] = *(const __half2*)(nd + 256 + cb);
    }

    // ---- MMA1: E3 = A @ Wu3 ----
    float acc[4][4];
    #pragma unroll
    for (int nt = 0; nt < 4; nt++)
        #pragma unroll
        for (int j = 0; j < 4; j++) acc[nt][j] = 0.f;
    #pragma unroll
    for (int kk = 0; kk < 8; kk++) {
        unsigned a0 = sAu[(m0 + g)     * 68 + kk * 8 + q];
        unsigned a1 = sAu[(m0 + g + 8) * 68 + kk * 8 + q];
        unsigned a2 = sAu[(m0 + g)     * 68 + kk * 8 + q + 4];
        unsigned a3 = sAu[(m0 + g + 8) * 68 + kk * 8 + q + 4];
        int b4 = ng * 512 + kk * 64 + lane;
        uint4 w0 = __ldg(&Wf[b4]);
        uint4 w1 = __ldg(&Wf[b4 + 32]);
        mma_tf32(acc[0], a0, a1, a2, a3, w0.x, w0.y);
        mma_tf32(acc[1], a0, a1, a2, a3, w0.z, w0.w);
        mma_tf32(acc[2], a0, a1, a2, a3, w1.x, w1.y);
        mma_tf32(acc[3], a0, a1, a2, a3, w1.z, w1.w);
    }
    #pragma unroll
    for (int nt = 0; nt < 4; nt++) {
        int col = n0 + nt * 8 + q * 2;
        sRes[(m0 + g)     * 68 + col]     = acc[nt][0];
        sRes[(m0 + g)     * 68 + col + 1] = acc[nt][1];
        sRes[(m0 + g + 8) * 68 + col]     = acc[nt][2];
        sRes[(m0 + g + 8) * 68 + col + 1] = acc[nt][3];
    }
    // gate
    if (t < 64) {
        float s = 0.f;
        #pragma unroll 16
        for (int k = 0; k < 64; k++) s += __uint_as_float(sAu[t * 68 + k]) * sWa[k];
        float a1v = *(const float*)(nb + sSrc[t] + 384);
        float a2v = *(const float*)(nb + sDst[t] + 388);
        sGate[t] = 1.f / (1.f + __expf(-lrelu_f(a1v + a2v + s + g_battn)));
    }
    __syncthreads();

    // ---- Phase B1: process prefetched batch, pipeline second batch ----
    float2 bu2 = make_float2(bupd[c], bupd[c + 1]);
    float2 cv2 = make_float2(g_cvec[c], g_cvec[c + 1]);

    // issue second-batch loads
    __half2 I1[4], I2[4], I3s[4], I3d[4];
    #pragma unroll
    for (int i = 0; i < 4; i++) {
        int e = ebase + 4 + i;
        const char* ns = nb + sSrc[e];
        const char* nd = nb + sDst[e];
        I1[i]  = *(const __half2*)(ns + cb);
        I2[i]  = *(const __half2*)(nd + 128 + cb);
        I3s[i] = *(const __half2*)(ns + 256 + cb);
        I3d[i] = *(const __half2*)(nd + 256 + cb);
    }
    // process batch 1 (prefetched before MMA1)
    #pragma unroll
    for (int i = 0; i < 4; i++) {
        int e = ebase + i;
        float gt = sGate[e];
        float2 p1 = __half22float2(H1[i]);
        float2 p2 = __half22float2(H2[i]);
        float2 p3a = __half22float2(H3s[i]);
        float2 p3b = __half22float2(H3d[i]);
        float2 e3 = *(const float2*)&sRes[e * 68 + c];
        float2 u;
        u.x = gt * (p1.x + p2.x + e3.x + bu2.x);
        u.y = gt * (p1.y + p2.y + e3.y + bu2.y);
        *(float2*)&sUf[e * 64 + c] = u;
        *(uint2*)&sAu[e * 68 + c] = make_uint2(f2tf32(u.x), f2tf32(u.y));
        *(float2*)&sRes[e * 68 + c] = make_float2(p3a.x + p3b.x, p3a.y + p3b.y);
    }
    // process batch 2
    #pragma unroll
    for (int i = 0; i < 4; i++) {
        int e = ebase + 4 + i;
        float gt = sGate[e];
        float2 p1 = __half22float2(I1[i]);
        float2 p2 = __half22float2(I2[i]);
        float2 p3a = __half22float2(I3s[i]);
        float2 p3b = __half22float2(I3d[i]);
        float2 e3 = *(const float2*)&sRes[e * 68 + c];
        float2 u;
        u.x = gt * (p1.x + p2.x + e3.x + bu2.x);
        u.y = gt * (p1.y + p2.y + e3.y + bu2.y);
        *(float2*)&sUf[e * 64 + c] = u;
        *(uint2*)&sAu[e * 68 + c] = make_uint2(f2tf32(u.x), f2tf32(u.y));
        *(float2*)&sRes[e * 68 + c] = make_float2(p3a.x + p3b.x, p3a.y + p3b.y);
    }
    __syncthreads();

    // ---- MMA2: T = updated @ W_edge (reads sAu; T stored back into sAu) ----
    #pragma unroll
    for (int nt = 0; nt < 4; nt++)
        #pragma unroll
        for (int j = 0; j < 4; j++) acc[nt][j] = 0.f;
    #pragma unroll
    for (int kk = 0; kk < 8; kk++) {
        unsigned a0 = sAu[(m0 + g)     * 68 + kk * 8 + q];
        unsigned a1 = sAu[(m0 + g + 8) * 68 + kk * 8 + q];
        unsigned a2 = sAu[(m0 + g)     * 68 + kk * 8 + q + 4];
        unsigned a3 = sAu[(m0 + g + 8) * 68 + kk * 8 + q + 4];
        int b4 = 1024 + ng * 512 + kk * 64 + lane;
        uint4 w0 = __ldg(&Wf[b4]);
        uint4 w1 = __ldg(&Wf[b4 + 32]);
        mma_tf32(acc[0], a0, a1, a2, a3, w0.x, w0.y);
        mma_tf32(acc[1], a0, a1, a2, a3, w0.z, w0.w);
        mma_tf32(acc[2], a0, a1, a2, a3, w1.x, w1.y);
        mma_tf32(acc[3], a0, a1, a2, a3, w1.z, w1.w);
    }
    __syncthreads();   // all sAu fragment reads complete
    #pragma unroll
    for (int nt = 0; nt < 4; nt++) {
        int col = n0 + nt * 8 + q * 2;
        sAu[(m0 + g)     * 68 + col]     = __float_as_uint(acc[nt][0]);
        sAu[(m0 + g)     * 68 + col + 1] = __float_as_uint(acc[nt][1]);
        sAu[(m0 + g + 8) * 68 + col]     = __float_as_uint(acc[nt][2]);
        sAu[(m0 + g + 8) * 68 + col + 1] = __float_as_uint(acc[nt][3]);
    }
    __syncthreads();

    // ---- Phase B2: pure smem — z = lrelu(T + P3sum + cvec); softmax; store ----
    float2 zs[8];
    #pragma unroll
    for (int i = 0; i < 8; i++) {
        int e = ebase + i;
        bool v = (e0g + e) < E;
        uint2 tb = *(const uint2*)&sAu[e * 68 + c];
        float2 p3 = *(const float2*)&sRes[e * 68 + c];
        float zx = lrelu_f(__uint_as_float(tb.x) + p3.x + cv2.x);
        float zy = lrelu_f(__uint_as_float(tb.y) + p3.y + cv2.y);
        zs[i] = v ? make_float2(zx, zy) : make_float2(-1e30f, -1e30f);
    }
    float2 ml = make_float2(-1e30f, -1e30f);
    #pragma unroll
    for (int i = 0; i < 8; i++) {
        ml.x = fmaxf(ml.x, zs[i].x);
        ml.y = fmaxf(ml.y, zs[i].y);
    }
    *(float2*)&sPM[warp * 68 + c] = ml;
    __syncthreads();
    float2 mb = make_float2(-1e30f, -1e30f);
    #pragma unroll
    for (int w2 = 0; w2 < 8; w2++) {
        mb.x = fmaxf(mb.x, sPM[w2 * 68 + c]);
        mb.y = fmaxf(mb.y, sPM[w2 * 68 + c + 1]);
    }
    float2 sl = make_float2(0.f, 0.f);
    #pragma unroll
    for (int i = 0; i < 8; i++) {
        int e = ebase + i;
        if ((e0g + e) < E) {
            float ex = __expf(zs[i].x - mb.x);
            float ey = __expf(zs[i].y - mb.y);
            sl.x += ex; sl.y += ey;
            float2 u = *(const float2*)&sUf[e * 64 + c];
            float2 o = make_float2(u.x * ex, u.y * ey);
            *(float2*)&out[(size_t)(e0g + e) * 64 + c] = o;
        }
    }
    *(float2*)&sPS[warp * 68 + c] = sl;
    __syncthreads();
    if (warp == 0) {
        float sx = 0.f, sy = 0.f;
        #pragma unroll
        for (int w2 = 0; w2 < 8; w2++) {
            sx += sPS[w2 * 68 + c];
            sy += sPS[w2 * 68 + c + 1];
        }
        g_partM[c * MAXNB + blockIdx.x]       = mb.x;
        g_partM[(c + 1) * MAXNB + blockIdx.x] = mb.y;
        g_partS[c * MAXNB + blockIdx.x]       = sx;
        g_partS[(c + 1) * MAXNB + blockIdx.x] = sy;
    }
}

__global__ void k_combine(int NB)
{
    int c = blockIdx.x, t = threadIdx.x;
    float m = -1e30f, s = 0.f;
    for (int b = t; b < NB; b += 256) {
        float mb = g_partM[c * MAXNB + b], sb = g_partS[c * MAXNB + b];
        float M2 = fmaxf(m, mb);
        s = s * __expf(m - M2) + sb * __expf(mb - M2);
        m = M2;
    }
    __shared__ float sm[256], ss[256];
    sm[t] = m; ss[t] = s; __syncthreads();
    for (int off = 128; off > 0; off >>= 1) {
        if (t < off) {
            float M2 = fmaxf(sm[t], sm[t + off]);
            ss[t] = ss[t] * __expf(sm[t] - M2) + ss[t + off] * __expf(sm[t + off] - M2);
            sm[t] = M2;
        }
        __syncthreads();
    }
    if (t == 0) { g_Mg[c] = sm[0]; g_invS[c] = 1.f / ss[0]; }
}

__global__ void k_pass2(float4* __restrict__ out, int total4)
{
    int i = blockIdx.x * 256 + threadIdx.x;
    if (i >= total4) return;
    int c0 = (i * 4) & 63;
    int b  = i >> 10;
    float4 o = out[i];
    o.x *= __expf(g_partM[(c0 + 0) * MAXNB + b] - g_Mg[c0 + 0]) * g_invS[c0 + 0];
    o.y *= __expf(g_partM[(c0 + 1) * MAXNB + b] - g_Mg[c0 + 1]) * g_invS[c0 + 1];
    o.z *= __expf(g_partM[(c0 + 2) * MAXNB + b] - g_Mg[c0 + 2]) * g_invS[c0 + 2];
    o.w *= __expf(g_partM[(c0 + 3) * MAXNB + b] - g_Mg[c0 + 3]) * g_invS[c0 + 3];
    out[i] = o;
}

extern "C" void kernel_launch(void* const* d_in, const int* in_sizes, int n_in,
                              void* d_out, int out_size)
{
    const float* eemb = (const float*)d_in[0];
    const float* ne   = (const float*)d_in[2];
    const float* Wa   = (const float*)d_in[3];
    const float* ba   = (const float*)d_in[4];
    const float* Wu   = (const float*)d_in[5];
    const float* bu   = (const float*)d_in[6];
    const float* We   = (const float*)d_in[7];
    const float* be   = (const float*)d_in[8];
    const float* Wn   = (const float*)d_in[9];
    const float* bn   = (const float*)d_in[10];
    const void*  eidx = d_in[11];
    float* out = (float*)d_out;

    int E = in_sizes[0] / 64;
    int N = in_sizes[2] / 64;
    int NB = (E + 63) / 64;

    cudaFuncSetAttribute(k_edge, cudaFuncAttributeMaxDynamicSharedMemorySize, SMEM_BYTES);

    k_prep<<<1, 256>>>(Wa, ba, Wu, bu, We, be, Wn, bn, (const unsigned*)eidx);
    k_node<<<(N + 31) / 32, 256>>>(ne, N);
    k_mark<<<1, 64>>>();
    k_edge<<<NB, 256, SMEM_BYTES>>>(eemb, eidx, bu, out, E);
    k_combine<<<64, 256>>>(NB);
    int total4 = E * 16;
    k_pass2<<<(total4 + 255) / 256, 256>>>((float4*)out, total4);
}

// round 12
// speedup vs baseline: 1.6831x; 1.1796x over previous
#include <cuda_runtime.h>
#include <cuda_fp16.h>

#define SLOPE 0.2f
#define NRB   512                  // node row bytes: P1 h[64] | P2 h[64] | P3 h[64] | a1 f | a2 f | pad
#define MAXN  100352
#define MAXE  1000192
#define MAXNB (MAXE / 64)

__device__ float4   g_node[(size_t)MAXN * (NRB / 16)];   // 51MB, 512B/node
__device__ float    g_partM[64 * MAXNB];
__device__ float    g_partS[64 * MAXNB];
__device__ unsigned g_W2h[4096];    // k_edge weights fp16, fragment-major [ph][ng][kk(4)][lane][8]
__device__ unsigned g_Wnf[16384];   // k_node weights tf32, fragment-major [ng(4)][kk(8)][lane(32)][16]
__device__ float    g_Wa3[64];
__device__ float    g_cvec[64];
__device__ float    g_Mg[64];
__device__ float    g_invS[64];
__device__ float    g_battn;
__device__ int      g_idx64;

__device__ __forceinline__ float lrelu_f(float x) { return x >= 0.f ? x : SLOPE * x; }
__device__ __forceinline__ unsigned f2tf32(float f) {
    unsigned u; asm("cvt.rna.tf32.f32 %0, %1;" : "=r"(u) : "f"(f)); return u;
}
__device__ __forceinline__ void mma_tf32(float* c, unsigned a0, unsigned a1, unsigned a2, unsigned a3,
                                         unsigned b0, unsigned b1) {
    asm volatile("mma.sync.aligned.m16n8k8.row.col.f32.tf32.tf32.f32 "
                 "{%0,%1,%2,%3}, {%4,%5,%6,%7}, {%8,%9}, {%0,%1,%2,%3};"
                 : "+f"(c[0]), "+f"(c[1]), "+f"(c[2]), "+f"(c[3])
                 : "r"(a0), "r"(a1), "r"(a2), "r"(a3), "r"(b0), "r"(b1));
}
__device__ __forceinline__ void mma_f16(float* c, unsigned a0, unsigned a1, unsigned a2, unsigned a3,
                                        unsigned b0, unsigned b1) {
    asm volatile("mma.sync.aligned.m16n8k16.row.col.f32.f16.f16.f32 "
                 "{%0,%1,%2,%3}, {%4,%5,%6,%7}, {%8,%9}, {%0,%1,%2,%3};"
                 : "+f"(c[0]), "+f"(c[1]), "+f"(c[2]), "+f"(c[3])
                 : "r"(a0), "r"(a1), "r"(a2), "r"(a3), "r"(b0), "r"(b1));
}

__device__ __forceinline__ float wn_val(int k, int col,
                                        const float* W_upd, const float* W_node, const float* W_attn)
{
    if (col < 64)   return W_upd[k * 64 + col];
    if (col < 128)  return W_upd[(64 + k) * 64 + (col - 64)];
    if (col < 192)  return W_node[k * 64 + (col - 128)];
    if (col == 192) return W_attn[k];
    if (col == 193) return W_attn[64 + k];
    return 0.f;
}

__global__ void k_prep(const float* __restrict__ W_attn, const float* __restrict__ b_attn,
                       const float* __restrict__ W_upd,  const float* __restrict__ b_upd,
                       const float* __restrict__ W_edge, const float* __restrict__ b_edge,
                       const float* __restrict__ W_node, const float* __restrict__ b_node,
                       const unsigned* __restrict__ eidx_raw)
{
    int t = threadIdx.x;
    // fp16 fragment-major edge weights: idx = (((ph*2+ng)*4+kk)*32+lane)*8 + r
    for (int idx = t; idx < 4096; idx += 256) {
        int r    = idx & 7;
        int lane = (idx >> 3) & 31;
        int kk   = (idx >> 8) & 3;
        int ng   = (idx >> 10) & 1;
        int ph   = (idx >> 11) & 1;
        int g = lane >> 2, q = lane & 3;
        int nt = r >> 1, hb = r & 1;
        int kb = kk * 16 + 2 * q + hb * 8;
        int c  = ng * 32 + nt * 8 + g;
        float v0 = (ph == 0) ? W_upd[(128 + kb) * 64 + c]     : W_edge[kb * 64 + c];
        float v1 = (ph == 0) ? W_upd[(128 + kb + 1) * 64 + c] : W_edge[(kb + 1) * 64 + c];
        __half2 h = __floats2half2_rn(v0, v1);
        g_W2h[idx] = *(unsigned*)&h;
    }
    for (int idx = t; idx < 16384; idx += 256) {
        int j    = idx & 15;
        int lane = (idx >> 4) & 31;
        int kk   = (idx >> 9) & 7;
        int ng   = (idx >> 12) & 3;
        float v = 0.f;
        if (j < 14) {
            int g = lane >> 2, q = lane & 3;
            int nt = j >> 1, b = j & 1;
            int k = kk * 8 + q + b * 4;
            int col = ng * 56 + nt * 8 + g;
            v = wn_val(k, col, W_upd, W_node, W_attn);
        }
        g_Wnf[idx] = f2tf32(v);
    }
    if (t < 64) {
        g_cvec[t] = b_edge[t] + 2.f * b_node[t];
        g_Wa3[t]  = W_attn[128 + t];
    }
    if (t == 0) {
        g_battn = b_attn[0];
        int is64 = 1;
        for (int i = 0; i < 32; i++)
            if (eidx_raw[2 * i + 1] != 0u) { is64 = 0; break; }
        g_idx64 = is64;
    }
}

// tf32 MMA node precompute: 32 nodes/block, 194 used cols, K=64
__global__ __launch_bounds__(256) void k_node(const float* __restrict__ ne, int N)
{
    __shared__ unsigned sX[32 * 68];
    __shared__ float    sOut[32 * 228];
    int t = threadIdx.x;
    int n0 = blockIdx.x * 32;

    for (int i = t; i < 32 * 64; i += 256) {
        int n = n0 + (i >> 6);
        float v = (n < N) ? ne[(size_t)n * 64 + (i & 63)] : 0.f;
        sX[(i >> 6) * 68 + (i & 63)] = f2tf32(v);
    }
    __syncthreads();

    int lane = t & 31, warp = t >> 5;
    int m0 = (warp & 1) * 16;
    int ng = warp >> 1;
    int n0c = ng * 56;
    int g = lane >> 2, q = lane & 3;
    const uint4* W4 = (const uint4*)g_Wnf;
    const uint2* W2 = (const uint2*)g_Wnf;

    float acc[7][4];
    #pragma unroll
    for (int nt = 0; nt < 7; nt++)
        #pragma unroll
        for (int j = 0; j < 4; j++) acc[nt][j] = 0.f;

    #pragma unroll
    for (int kk = 0; kk < 8; kk++) {
        unsigned a0 = sX[(m0 + g)     * 68 + kk * 8 + q];
        unsigned a1 = sX[(m0 + g + 8) * 68 + kk * 8 + q];
        unsigned a2 = sX[(m0 + g)     * 68 + kk * 8 + q + 4];
        unsigned a3 = sX[(m0 + g + 8) * 68 + kk * 8 + q + 4];
        int base = ((ng * 8 + kk) * 32 + lane);
        uint4 w0 = __ldg(&W4[base * 4]);
        uint4 w1 = __ldg(&W4[base * 4 + 1]);
        uint4 w2 = __ldg(&W4[base * 4 + 2]);
        uint2 w3 = __ldg(&W2[base * 8 + 6]);
        mma_tf32(acc[0], a0, a1, a2, a3, w0.x, w0.y);
        mma_tf32(acc[1], a0, a1, a2, a3, w0.z, w0.w);
        mma_tf32(acc[2], a0, a1, a2, a3, w1.x, w1.y);
        mma_tf32(acc[3], a0, a1, a2, a3, w1.z, w1.w);
        mma_tf32(acc[4], a0, a1, a2, a3, w2.x, w2.y);
        mma_tf32(acc[5], a0, a1, a2, a3, w2.z, w2.w);
        mma_tf32(acc[6], a0, a1, a2, a3, w3.x, w3.y);
    }
    #pragma unroll
    for (int nt = 0; nt < 7; nt++) {
        int col = n0c + nt * 8 + q * 2;
        sOut[(m0 + g)     * 228 + col]     = acc[nt][0];
        sOut[(m0 + g)     * 228 + col + 1] = acc[nt][1];
        sOut[(m0 + g + 8) * 228 + col]     = acc[nt][2];
        sOut[(m0 + g + 8) * 228 + col + 1] = acc[nt][3];
    }
    __syncthreads();

    for (int i = t; i < 32 * 64; i += 256) {
        int n = i >> 6, j = i & 63;
        if (n0 + n >= N) continue;
        char* dst = (char*)g_node + (size_t)(n0 + n) * NRB;
        *(__half2*)(dst + j * 4) = __floats2half2_rn(sOut[n * 228 + 2 * j], sOut[n * 228 + 2 * j + 1]);
    }
    for (int i = t; i < 32 * 32; i += 256) {
        int n = i >> 5, j = i & 31;
        if (n0 + n >= N) continue;
        char* dst = (char*)g_node + (size_t)(n0 + n) * NRB;
        *(__half2*)(dst + 256 + j * 4) = __floats2half2_rn(sOut[n * 228 + 128 + 2 * j], sOut[n * 228 + 129 + 2 * j]);
    }
    if (t < 32 && n0 + t < N) {
        char* dst = (char*)g_node + (size_t)(n0 + t) * NRB;
        *(float*)(dst + 384) = sOut[t * 228 + 192];
        *(float*)(dst + 388) = sOut[t * 228 + 193];
    }
}

// dummy kernel — keeps k_edge in the fixed ncu capture slot
__global__ void k_mark() { if (threadIdx.x < 64) g_Mg[threadIdx.x] = 0.f; }

// smem (u32): sAh[64*36] fp16 tile | sRes[64*68] | sUf[64*64] | sPM[8*68] | sPS[8*68] | misc
#define SAH_U (64 * 36)
#define SR_F  (64 * 68)
#define SUF_F (64 * 64)
#define SP_F  (8 * 68)
#define SMEM_F (SAH_U + SR_F + SUF_F + 2 * SP_F + 256)
#define SMEM_BYTES (SMEM_F * 4)

__global__ __launch_bounds__(256, 4) void k_edge(const float* __restrict__ eemb,
                                                 const void*  __restrict__ eidx,
                                                 const float* __restrict__ bupd,
                                                 float*       __restrict__ out,
                                                 int E)
{
    extern __shared__ float smem[];
    unsigned* sAh   = (unsigned*)smem;       // fp16: edge tile → updated
    float*    sRes  = smem + SAH_U;          // E3 → P3sum → P3sum+T
    float*    sUf   = smem + SAH_U + SR_F;   // updated fp32 (pitch 64)
    float*    sPM   = smem + SAH_U + SR_F + SUF_F;
    float*    sPS   = sPM + SP_F;
    float*    sWa   = sPS + SP_F;
    float*    sGate = sWa + 64;
    int*      sSrc  = (int*)(sGate + 64);    // byte offsets into g_node
    int*      sDst  = sSrc + 64;

    int t = threadIdx.x;
    int e0g = blockIdx.x * 64;
    int idx64 = g_idx64;

    if (t < 128) {
        int j = t & 63;
        int ee = min(e0g + j, E - 1);
        size_t pos = (t < 64) ? (size_t)ee : (size_t)E + (size_t)ee;
        int v = idx64 ? (int)((const long long*)eidx)[pos] : ((const int*)eidx)[pos];
        if (t < 64) sSrc[j] = v * NRB; else sDst[j] = v * NRB;
    }
    if (t >= 128 && t < 192) sWa[t - 128] = g_Wa3[t - 128];
    for (int i = t; i < 64 * 32; i += 256) {
        int e = i >> 5, k2 = i & 31;
        int ee = min(e0g + e, E - 1);
        float2 v = *(const float2*)(eemb + (size_t)ee * 64 + k2 * 2);
        __half2 h = __floats2half2_rn(v.x, v.y);
        sAh[e * 36 + k2] = *(unsigned*)&h;
    }
    __syncthreads();

    int lane = t & 31, warp = t >> 5;
    int m0 = (warp & 3) * 16;
    int ng = warp >> 2;
    int n0 = ng * 32;
    int g = lane >> 2, q = lane & 3;
    const uint4* Wh = (const uint4*)g_W2h;    // 1024 uint4; phase1 starts at 512
    const char* nb = (const char*)g_node;

    int c = lane * 2;
    int cb = lane * 4;
    int ebase = warp * 8;

    // ---- prefetch gathers for edges ebase..ebase+3 (overlap with MMA1) ----
    __half2 H1[4], H2[4], H3s[4], H3d[4];
    #pragma unroll
    for (int i = 0; i < 4; i++) {
        int e = ebase + i;
        const char* ns = nb + sSrc[e];
        const char* nd = nb + sDst[e];
        H1[i]  = *(const __half2*)(ns + cb);
        H2[i]  = *(const __half2*)(nd + 128 + cb);
        H3s[i] = *(const __half2*)(ns + 256 + cb);
        H3d[i] = *(const __half2*)(nd + 256 + cb);
    }

    // ---- MMA1 (fp16, K=16/step): E3 = A @ Wu3 ----
    float acc[4][4];
    #pragma unroll
    for (int nt = 0; nt < 4; nt++)
        #pragma unroll
        for (int j = 0; j < 4; j++) acc[nt][j] = 0.f;
    #pragma unroll
    for (int kk = 0; kk < 4; kk++) {
        unsigned a0 = sAh[(m0 + g)     * 36 + kk * 8 + q];
        unsigned a1 = sAh[(m0 + g + 8) * 36 + kk * 8 + q];
        unsigned a2 = sAh[(m0 + g)     * 36 + kk * 8 + q + 4];
        unsigned a3 = sAh[(m0 + g + 8) * 36 + kk * 8 + q + 4];
        int b8 = (ng * 4 + kk) * 64 + lane * 2;
        uint4 w0 = __ldg(&Wh[b8]);
        uint4 w1 = __ldg(&Wh[b8 + 1]);
        mma_f16(acc[0], a0, a1, a2, a3, w0.x, w0.y);
        mma_f16(acc[1], a0, a1, a2, a3, w0.z, w0.w);
        mma_f16(acc[2], a0, a1, a2, a3, w1.x, w1.y);
        mma_f16(acc[3], a0, a1, a2, a3, w1.z, w1.w);
    }
    #pragma unroll
    for (int nt = 0; nt < 4; nt++) {
        int col = n0 + nt * 8 + q * 2;
        sRes[(m0 + g)     * 68 + col]     = acc[nt][0];
        sRes[(m0 + g)     * 68 + col + 1] = acc[nt][1];
        sRes[(m0 + g + 8) * 68 + col]     = acc[nt][2];
        sRes[(m0 + g + 8) * 68 + col + 1] = acc[nt][3];
    }
    // gate (reads fp16 edge tile)
    if (t < 64) {
        float s = 0.f;
        #pragma unroll 8
        for (int k2 = 0; k2 < 32; k2++) {
            unsigned hb = sAh[t * 36 + k2];
            float2 a = __half22float2(*(__half2*)&hb);
            s += a.x * sWa[2 * k2] + a.y * sWa[2 * k2 + 1];
        }
        float a1v = *(const float*)(nb + sSrc[t] + 384);
        float a2v = *(const float*)(nb + sDst[t] + 388);
        sGate[t] = 1.f / (1.f + __expf(-lrelu_f(a1v + a2v + s + g_battn)));
    }
    __syncthreads();

    // ---- Phase B1: prefetched batch + pipelined second batch ----
    float2 bu2 = make_float2(bupd[c], bupd[c + 1]);
    float2 cv2 = make_float2(g_cvec[c], g_cvec[c + 1]);

    __half2 I1[4], I2[4], I3s[4], I3d[4];
    #pragma unroll
    for (int i = 0; i < 4; i++) {
        int e = ebase + 4 + i;
        const char* ns = nb + sSrc[e];
        const char* nd = nb + sDst[e];
        I1[i]  = *(const __half2*)(ns + cb);
        I2[i]  = *(const __half2*)(nd + 128 + cb);
        I3s[i] = *(const __half2*)(ns + 256 + cb);
        I3d[i] = *(const __half2*)(nd + 256 + cb);
    }
    #pragma unroll
    for (int i = 0; i < 4; i++) {
        int e = ebase + i;
        float gt = sGate[e];
        float2 p1 = __half22float2(H1[i]);
        float2 p2 = __half22float2(H2[i]);
        float2 p3a = __half22float2(H3s[i]);
        float2 p3b = __half22float2(H3d[i]);
        float2 e3 = *(const float2*)&sRes[e * 68 + c];
        float2 u;
        u.x = gt * (p1.x + p2.x + e3.x + bu2.x);
        u.y = gt * (p1.y + p2.y + e3.y + bu2.y);
        *(float2*)&sUf[e * 64 + c] = u;
        __half2 uh = __floats2half2_rn(u.x, u.y);
        sAh[e * 36 + lane] = *(unsigned*)&uh;
        *(float2*)&sRes[e * 68 + c] = make_float2(p3a.x + p3b.x, p3a.y + p3b.y);
    }
    #pragma unroll
    for (int i = 0; i < 4; i++) {
        int e = ebase + 4 + i;
        float gt = sGate[e];
        float2 p1 = __half22float2(I1[i]);
        float2 p2 = __half22float2(I2[i]);
        float2 p3a = __half22float2(I3s[i]);
        float2 p3b = __half22float2(I3d[i]);
        float2 e3 = *(const float2*)&sRes[e * 68 + c];
        float2 u;
        u.x = gt * (p1.x + p2.x + e3.x + bu2.x);
        u.y = gt * (p1.y + p2.y + e3.y + bu2.y);
        *(float2*)&sUf[e * 64 + c] = u;
        __half2 uh = __floats2half2_rn(u.x, u.y);
        sAh[e * 36 + lane] = *(unsigned*)&uh;
        *(float2*)&sRes[e * 68 + c] = make_float2(p3a.x + p3b.x, p3a.y + p3b.y);
    }
    __syncthreads();

    // ---- MMA2 (fp16): T = updated @ W_edge; accumulate T into sRes (P3sum) ----
    #pragma unroll
    for (int nt = 0; nt < 4; nt++)
        #pragma unroll
        for (int j = 0; j < 4; j++) acc[nt][j] = 0.f;
    #pragma unroll
    for (int kk = 0; kk < 4; kk++) {
        unsigned a0 = sAh[(m0 + g)     * 36 + kk * 8 + q];
        unsigned a1 = sAh[(m0 + g + 8) * 36 + kk * 8 + q];
        unsigned a2 = sAh[(m0 + g)     * 36 + kk * 8 + q + 4];
        unsigned a3 = sAh[(m0 + g + 8) * 36 + kk * 8 + q + 4];
        int b8 = 512 + (ng * 4 + kk) * 64 + lane * 2;    // phase 1 (uint4 base = 512)
        uint4 w0 = __ldg(&Wh[b8]);
        uint4 w1 = __ldg(&Wh[b8 + 1]);
        mma_f16(acc[0], a0, a1, a2, a3, w0.x, w0.y);
        mma_f16(acc[1], a0, a1, a2, a3, w0.z, w0.w);
        mma_f16(acc[2], a0, a1, a2, a3, w1.x, w1.y);
        mma_f16(acc[3], a0, a1, a2, a3, w1.z, w1.w);
    }
    __syncthreads();
    #pragma unroll
    for (int nt = 0; nt < 4; nt++) {
        int col = n0 + nt * 8 + q * 2;
        sRes[(m0 + g)     * 68 + col]     += acc[nt][0];
        sRes[(m0 + g)     * 68 + col + 1] += acc[nt][1];
        sRes[(m0 + g + 8) * 68 + col]     += acc[nt][2];
        sRes[(m0 + g + 8) * 68 + col + 1] += acc[nt][3];
    }
    __syncthreads();

    // ---- Phase B2: z = lrelu(sRes + cvec); softmax; store ----
    float2 zs[8];
    #pragma unroll
    for (int i = 0; i < 8; i++) {
        int e = ebase + i;
        bool v = (e0g + e) < E;
        float2 tv = *(const float2*)&sRes[e * 68 + c];
        float zx = lrelu_f(tv.x + cv2.x);
        float zy = lrelu_f(tv.y + cv2.y);
        zs[i] = v ? make_float2(zx, zy) : make_float2(-1e30f, -1e30f);
    }
    float2 ml = make_float2(-1e30f, -1e30f);
    #pragma unroll
    for (int i = 0; i < 8; i++) {
        ml.x = fmaxf(ml.x, zs[i].x);
        ml.y = fmaxf(ml.y, zs[i].y);
    }
    *(float2*)&sPM[warp * 68 + c] = ml;
    __syncthreads();
    float2 mb = make_float2(-1e30f, -1e30f);
    #pragma unroll
    for (int w2 = 0; w2 < 8; w2++) {
        mb.x = fmaxf(mb.x, sPM[w2 * 68 + c]);
        mb.y = fmaxf(mb.y, sPM[w2 * 68 + c + 1]);
    }
    float2 sl = make_float2(0.f, 0.f);
    #pragma unroll
    for (int i = 0; i < 8; i++) {
        int e = ebase + i;
        if ((e0g + e) < E) {
            float ex = __expf(zs[i].x - mb.x);
            float ey = __expf(zs[i].y - mb.y);
            sl.x += ex; sl.y += ey;
            float2 u = *(const float2*)&sUf[e * 64 + c];
            float2 o = make_float2(u.x * ex, u.y * ey);
            *(float2*)&out[(size_t)(e0g + e) * 64 + c] = o;
        }
    }
    *(float2*)&sPS[warp * 68 + c] = sl;
    __syncthreads();
    if (warp == 0) {
        float sx = 0.f, sy = 0.f;
        #pragma unroll
        for (int w2 = 0; w2 < 8; w2++) {
            sx += sPS[w2 * 68 + c];
            sy += sPS[w2 * 68 + c + 1];
        }
        g_partM[c * MAXNB + blockIdx.x]       = mb.x;
        g_partM[(c + 1) * MAXNB + blockIdx.x] = mb.y;
        g_partS[c * MAXNB + blockIdx.x]       = sx;
        g_partS[(c + 1) * MAXNB + blockIdx.x] = sy;
    }
}

__global__ void k_combine(int NB)
{
    int c = blockIdx.x, t = threadIdx.x;
    float m = -1e30f, s = 0.f;
    for (int b = t; b < NB; b += 256) {
        float mb = g_partM[c * MAXNB + b], sb = g_partS[c * MAXNB + b];
        float M2 = fmaxf(m, mb);
        s = s * __expf(m - M2) + sb * __expf(mb - M2);
        m = M2;
    }
    __shared__ float sm[256], ss[256];
    sm[t] = m; ss[t] = s; __syncthreads();
    for (int off = 128; off > 0; off >>= 1) {
        if (t < off) {
            float M2 = fmaxf(sm[t], sm[t + off]);
            ss[t] = ss[t] * __expf(sm[t] - M2) + ss[t + off] * __expf(sm[t + off] - M2);
            sm[t] = M2;
        }
        __syncthreads();
    }
    if (t == 0) { g_Mg[c] = sm[0]; g_invS[c] = 1.f / ss[0]; }
}

__global__ void k_pass2(float4* __restrict__ out, int total4)
{
    int i = blockIdx.x * 256 + threadIdx.x;
    if (i >= total4) return;
    int c0 = (i * 4) & 63;
    int b  = i >> 10;
    float4 o = out[i];
    o.x *= __expf(g_partM[(c0 + 0) * MAXNB + b] - g_Mg[c0 + 0]) * g_invS[c0 + 0];
    o.y *= __expf(g_partM[(c0 + 1) * MAXNB + b] - g_Mg[c0 + 1]) * g_invS[c0 + 1];
    o.z *= __expf(g_partM[(c0 + 2) * MAXNB + b] - g_Mg[c0 + 2]) * g_invS[c0 + 2];
    o.w *= __expf(g_partM[(c0 + 3) * MAXNB + b] - g_Mg[c0 + 3]) * g_invS[c0 + 3];
    out[i] = o;
}

extern "C" void kernel_launch(void* const* d_in, const int* in_sizes, int n_in,
                              void* d_out, int out_size)
{
    const float* eemb = (const float*)d_in[0];
    const float* ne   = (const float*)d_in[2];
    const float* Wa   = (const float*)d_in[3];
    const float* ba   = (const float*)d_in[4];
    const float* Wu   = (const float*)d_in[5];
    const float* bu   = (const float*)d_in[6];
    const float* We   = (const float*)d_in[7];
    const float* be   = (const float*)d_in[8];
    const float* Wn   = (const float*)d_in[9];
    const float* bn   = (const float*)d_in[10];
    const void*  eidx = d_in[11];
    float* out = (float*)d_out;

    int E = in_sizes[0] / 64;
    int N = in_sizes[2] / 64;
    int NB = (E + 63) / 64;

    cudaFuncSetAttribute(k_edge, cudaFuncAttributeMaxDynamicSharedMemorySize, SMEM_BYTES);

    k_prep<<<1, 256>>>(Wa, ba, Wu, bu, We, be, Wn, bn, (const unsigned*)eidx);
    k_node<<<(N + 31) / 32, 256>>>(ne, N);
    k_mark<<<1, 64>>>();
    k_edge<<<NB, 256, SMEM_BYTES>>>(eemb, eidx, bu, out, E);
    k_combine<<<64, 256>>>(NB);
    int total4 = E * 16;
    k_pass2<<<(total4 + 255) / 256, 256>>>((float4*)out, total4);
}

// round 13
// speedup vs baseline: 1.8602x; 1.1052x over previous
#include <cuda_runtime.h>
#include <cuda_fp16.h>

#define SLOPE 0.2f
#define NRB   512                  // node row bytes: P1 h[64] | P2 h[64] | P3 h[64] | a1 f | a2 f | pad
#define MAXN  100352
#define MAXE  1000192
#define MAXNB (MAXE / 64)

__device__ float4   g_node[(size_t)MAXN * (NRB / 16)];   // 51MB, 512B/node
__device__ float    g_partM[64 * MAXNB];
__device__ float    g_partS[64 * MAXNB];
__device__ float    g_factB[(size_t)MAXNB * 64];         // per-block per-channel rescale
__device__ unsigned g_W2h[4096];    // k_edge weights fp16, fragment-major [ph][ng][kk(4)][lane][8]
__device__ unsigned g_Wnf[16384];   // k_node weights tf32, fragment-major [ng(4)][kk(8)][lane(32)][16]
__device__ float    g_Wa3[64];
__device__ float    g_cvec[64];
__device__ float    g_Mg[64];
__device__ float    g_invS[64];
__device__ float    g_battn;
__device__ int      g_idx64;

__device__ __forceinline__ float lrelu_f(float x) { return x >= 0.f ? x : SLOPE * x; }
__device__ __forceinline__ unsigned f2tf32(float f) {
    unsigned u; asm("cvt.rna.tf32.f32 %0, %1;" : "=r"(u) : "f"(f)); return u;
}
__device__ __forceinline__ void mma_tf32(float* c, unsigned a0, unsigned a1, unsigned a2, unsigned a3,
                                         unsigned b0, unsigned b1) {
    asm volatile("mma.sync.aligned.m16n8k8.row.col.f32.tf32.tf32.f32 "
                 "{%0,%1,%2,%3}, {%4,%5,%6,%7}, {%8,%9}, {%0,%1,%2,%3};"
                 : "+f"(c[0]), "+f"(c[1]), "+f"(c[2]), "+f"(c[3])
                 : "r"(a0), "r"(a1), "r"(a2), "r"(a3), "r"(b0), "r"(b1));
}
__device__ __forceinline__ void mma_f16(float* c, unsigned a0, unsigned a1, unsigned a2, unsigned a3,
                                        unsigned b0, unsigned b1) {
    asm volatile("mma.sync.aligned.m16n8k16.row.col.f32.f16.f16.f32 "
                 "{%0,%1,%2,%3}, {%4,%5,%6,%7}, {%8,%9}, {%0,%1,%2,%3};"
                 : "+f"(c[0]), "+f"(c[1]), "+f"(c[2]), "+f"(c[3])
                 : "r"(a0), "r"(a1), "r"(a2), "r"(a3), "r"(b0), "r"(b1));
}

__device__ __forceinline__ float wn_val(int k, int col,
                                        const float* W_upd, const float* W_node, const float* W_attn)
{
    if (col < 64)   return W_upd[k * 64 + col];
    if (col < 128)  return W_upd[(64 + k) * 64 + (col - 64)];
    if (col < 192)  return W_node[k * 64 + (col - 128)];
    if (col == 192) return W_attn[k];
    if (col == 193) return W_attn[64 + k];
    return 0.f;
}

__global__ void k_prep(const float* __restrict__ W_attn, const float* __restrict__ b_attn,
                       const float* __restrict__ W_upd,  const float* __restrict__ b_upd,
                       const float* __restrict__ W_edge, const float* __restrict__ b_edge,
                       const float* __restrict__ W_node, const float* __restrict__ b_node,
                       const unsigned* __restrict__ eidx_raw)
{
    int t = threadIdx.x;
    for (int idx = t; idx < 4096; idx += 256) {
        int r    = idx & 7;
        int lane = (idx >> 3) & 31;
        int kk   = (idx >> 8) & 3;
        int ng   = (idx >> 10) & 1;
        int ph   = (idx >> 11) & 1;
        int g = lane >> 2, q = lane & 3;
        int nt = r >> 1, hb = r & 1;
        int kb = kk * 16 + 2 * q + hb * 8;
        int c  = ng * 32 + nt * 8 + g;
        float v0 = (ph == 0) ? W_upd[(128 + kb) * 64 + c]     : W_edge[kb * 64 + c];
        float v1 = (ph == 0) ? W_upd[(128 + kb + 1) * 64 + c] : W_edge[(kb + 1) * 64 + c];
        __half2 h = __floats2half2_rn(v0, v1);
        g_W2h[idx] = *(unsigned*)&h;
    }
    for (int idx = t; idx < 16384; idx += 256) {
        int j    = idx & 15;
        int lane = (idx >> 4) & 31;
        int kk   = (idx >> 9) & 7;
        int ng   = (idx >> 12) & 3;
        float v = 0.f;
        if (j < 14) {
            int g = lane >> 2, q = lane & 3;
            int nt = j >> 1, b = j & 1;
            int k = kk * 8 + q + b * 4;
            int col = ng * 56 + nt * 8 + g;
            v = wn_val(k, col, W_upd, W_node, W_attn);
        }
        g_Wnf[idx] = f2tf32(v);
    }
    if (t < 64) {
        g_cvec[t] = b_edge[t] + 2.f * b_node[t];
        g_Wa3[t]  = W_attn[128 + t];
    }
    if (t == 0) {
        g_battn = b_attn[0];
        int is64 = 1;
        for (int i = 0; i < 32; i++)
            if (eidx_raw[2 * i + 1] != 0u) { is64 = 0; break; }
        g_idx64 = is64;
    }
}

// tf32 MMA node precompute: 32 nodes/block, 194 used cols, K=64
__global__ __launch_bounds__(256) void k_node(const float* __restrict__ ne, int N)
{
    __shared__ unsigned sX[32 * 68];
    __shared__ float    sOut[32 * 228];
    int t = threadIdx.x;
    int n0 = blockIdx.x * 32;

    for (int i = t; i < 32 * 64; i += 256) {
        int n = n0 + (i >> 6);
        float v = (n < N) ? ne[(size_t)n * 64 + (i & 63)] : 0.f;
        sX[(i >> 6) * 68 + (i & 63)] = f2tf32(v);
    }
    __syncthreads();

    int lane = t & 31, warp = t >> 5;
    int m0 = (warp & 1) * 16;
    int ng = warp >> 1;
    int n0c = ng * 56;
    int g = lane >> 2, q = lane & 3;
    const uint4* W4 = (const uint4*)g_Wnf;
    const uint2* W2 = (const uint2*)g_Wnf;

    float acc[7][4];
    #pragma unroll
    for (int nt = 0; nt < 7; nt++)
        #pragma unroll
        for (int j = 0; j < 4; j++) acc[nt][j] = 0.f;

    #pragma unroll
    for (int kk = 0; kk < 8; kk++) {
        unsigned a0 = sX[(m0 + g)     * 68 + kk * 8 + q];
        unsigned a1 = sX[(m0 + g + 8) * 68 + kk * 8 + q];
        unsigned a2 = sX[(m0 + g)     * 68 + kk * 8 + q + 4];
        unsigned a3 = sX[(m0 + g + 8) * 68 + kk * 8 + q + 4];
        int base = ((ng * 8 + kk) * 32 + lane);
        uint4 w0 = __ldg(&W4[base * 4]);
        uint4 w1 = __ldg(&W4[base * 4 + 1]);
        uint4 w2 = __ldg(&W4[base * 4 + 2]);
        uint2 w3 = __ldg(&W2[base * 8 + 6]);
        mma_tf32(acc[0], a0, a1, a2, a3, w0.x, w0.y);
        mma_tf32(acc[1], a0, a1, a2, a3, w0.z, w0.w);
        mma_tf32(acc[2], a0, a1, a2, a3, w1.x, w1.y);
        mma_tf32(acc[3], a0, a1, a2, a3, w1.z, w1.w);
        mma_tf32(acc[4], a0, a1, a2, a3, w2.x, w2.y);
        mma_tf32(acc[5], a0, a1, a2, a3, w2.z, w2.w);
        mma_tf32(acc[6], a0, a1, a2, a3, w3.x, w3.y);
    }
    #pragma unroll
    for (int nt = 0; nt < 7; nt++) {
        int col = n0c + nt * 8 + q * 2;
        sOut[(m0 + g)     * 228 + col]     = acc[nt][0];
        sOut[(m0 + g)     * 228 + col + 1] = acc[nt][1];
        sOut[(m0 + g + 8) * 228 + col]     = acc[nt][2];
        sOut[(m0 + g + 8) * 228 + col + 1] = acc[nt][3];
    }
    __syncthreads();

    for (int i = t; i < 32 * 64; i += 256) {
        int n = i >> 6, j = i & 63;
        if (n0 + n >= N) continue;
        char* dst = (char*)g_node + (size_t)(n0 + n) * NRB;
        *(__half2*)(dst + j * 4) = __floats2half2_rn(sOut[n * 228 + 2 * j], sOut[n * 228 + 2 * j + 1]);
    }
    for (int i = t; i < 32 * 32; i += 256) {
        int n = i >> 5, j = i & 31;
        if (n0 + n >= N) continue;
        char* dst = (char*)g_node + (size_t)(n0 + n) * NRB;
        *(__half2*)(dst + 256 + j * 4) = __floats2half2_rn(sOut[n * 228 + 128 + 2 * j], sOut[n * 228 + 129 + 2 * j]);
    }
    if (t < 32 && n0 + t < N) {
        char* dst = (char*)g_node + (size_t)(n0 + t) * NRB;
        *(float*)(dst + 384) = sOut[t * 228 + 192];
        *(float*)(dst + 388) = sOut[t * 228 + 193];
    }
}

// dummy kernel — keeps k_edge in the fixed ncu capture slot
__global__ void k_mark() { if (threadIdx.x < 64) g_Mg[threadIdx.x] = 0.f; }

// smem (u32): sAh[64*36] fp16 tile | sRes[64*68] | sUf[64*64] | sPM[8*68] | sPS[8*68] | misc
#define SAH_U (64 * 36)
#define SR_F  (64 * 68)
#define SUF_F (64 * 64)
#define SP_F  (8 * 68)
#define SMEM_F (SAH_U + SR_F + SUF_F + 2 * SP_F + 256)
#define SMEM_BYTES (SMEM_F * 4)

__global__ __launch_bounds__(256, 4) void k_edge(const float* __restrict__ eemb,
                                                 const void*  __restrict__ eidx,
                                                 const float* __restrict__ bupd,
                                                 float*       __restrict__ out,
                                                 int E)
{
    extern __shared__ float smem[];
    unsigned* sAh   = (unsigned*)smem;       // fp16: edge tile → updated
    float*    sRes  = smem + SAH_U;          // E3 → P3sum → P3sum+T
    float*    sUf   = smem + SAH_U + SR_F;   // updated fp32 (pitch 64)
    float*    sPM   = smem + SAH_U + SR_F + SUF_F;
    float*    sPS   = sPM + SP_F;
    float*    sWa   = sPS + SP_F;
    float*    sGate = sWa + 64;
    int*      sSrc  = (int*)(sGate + 64);    // byte offsets into g_node
    int*      sDst  = sSrc + 64;

    int t = threadIdx.x;
    int e0g = blockIdx.x * 64;
    int idx64 = g_idx64;

    if (t < 128) {
        int j = t & 63;
        int ee = min(e0g + j, E - 1);
        size_t pos = (t < 64) ? (size_t)ee : (size_t)E + (size_t)ee;
        int v = idx64 ? (int)((const long long*)eidx)[pos] : ((const int*)eidx)[pos];
        if (t < 64) sSrc[j] = v * NRB; else sDst[j] = v * NRB;
    }
    if (t >= 128 && t < 192) sWa[t - 128] = g_Wa3[t - 128];
    for (int i = t; i < 64 * 32; i += 256) {
        int e = i >> 5, k2 = i & 31;
        int ee = min(e0g + e, E - 1);
        float2 v = *(const float2*)(eemb + (size_t)ee * 64 + k2 * 2);
        __half2 h = __floats2half2_rn(v.x, v.y);
        sAh[e * 36 + k2] = *(unsigned*)&h;
    }
    __syncthreads();

    int lane = t & 31, warp = t >> 5;
    int m0 = (warp & 3) * 16;
    int ng = warp >> 2;
    int n0 = ng * 32;
    int g = lane >> 2, q = lane & 3;
    const uint4* Wh = (const uint4*)g_W2h;    // 1024 uint4; phase1 starts at 512
    const char* nb = (const char*)g_node;

    int c = lane * 2;
    int cb = lane * 4;
    int ebase = warp * 8;

    // ---- prefetch gathers for edges ebase..ebase+3 (overlap with MMA1) ----
    __half2 H1[4], H2[4], H3s[4], H3d[4];
    #pragma unroll
    for (int i = 0; i < 4; i++) {
        int e = ebase + i;
        const char* ns = nb + sSrc[e];
        const char* nd = nb + sDst[e];
        H1[i]  = *(const __half2*)(ns + cb);
        H2[i]  = *(const __half2*)(nd + 128 + cb);
        H3s[i] = *(const __half2*)(ns + 256 + cb);
        H3d[i] = *(const __half2*)(nd + 256 + cb);
    }

    // ---- MMA1 (fp16, K=16/step): E3 = A @ Wu3 ----
    float acc[4][4];
    #pragma unroll
    for (int nt = 0; nt < 4; nt++)
        #pragma unroll
        for (int j = 0; j < 4; j++) acc[nt][j] = 0.f;
    #pragma unroll
    for (int kk = 0; kk < 4; kk++) {
        unsigned a0 = sAh[(m0 + g)     * 36 + kk * 8 + q];
        unsigned a1 = sAh[(m0 + g + 8) * 36 + kk * 8 + q];
        unsigned a2 = sAh[(m0 + g)     * 36 + kk * 8 + q + 4];
        unsigned a3 = sAh[(m0 + g + 8) * 36 + kk * 8 + q + 4];
        int b8 = (ng * 4 + kk) * 64 + lane * 2;
        uint4 w0 = __ldg(&Wh[b8]);
        uint4 w1 = __ldg(&Wh[b8 + 1]);
        mma_f16(acc[0], a0, a1, a2, a3, w0.x, w0.y);
        mma_f16(acc[1], a0, a1, a2, a3, w0.z, w0.w);
        mma_f16(acc[2], a0, a1, a2, a3, w1.x, w1.y);
        mma_f16(acc[3], a0, a1, a2, a3, w1.z, w1.w);
    }
    #pragma unroll
    for (int nt = 0; nt < 4; nt++) {
        int col = n0 + nt * 8 + q * 2;
        sRes[(m0 + g)     * 68 + col]     = acc[nt][0];
        sRes[(m0 + g)     * 68 + col + 1] = acc[nt][1];
        sRes[(m0 + g + 8) * 68 + col]     = acc[nt][2];
        sRes[(m0 + g + 8) * 68 + col + 1] = acc[nt][3];
    }
    // gate (reads fp16 edge tile)
    if (t < 64) {
        float s = 0.f;
        #pragma unroll 8
        for (int k2 = 0; k2 < 32; k2++) {
            unsigned hb = sAh[t * 36 + k2];
            float2 a = __half22float2(*(__half2*)&hb);
            s += a.x * sWa[2 * k2] + a.y * sWa[2 * k2 + 1];
        }
        float a1v = *(const float*)(nb + sSrc[t] + 384);
        float a2v = *(const float*)(nb + sDst[t] + 388);
        sGate[t] = 1.f / (1.f + __expf(-lrelu_f(a1v + a2v + s + g_battn)));
    }
    __syncthreads();

    // ---- Phase B1: prefetched batch + pipelined second batch ----
    float2 bu2 = make_float2(bupd[c], bupd[c + 1]);
    float2 cv2 = make_float2(g_cvec[c], g_cvec[c + 1]);

    __half2 I1[4], I2[4], I3s[4], I3d[4];
    #pragma unroll
    for (int i = 0; i < 4; i++) {
        int e = ebase + 4 + i;
        const char* ns = nb + sSrc[e];
        const char* nd = nb + sDst[e];
        I1[i]  = *(const __half2*)(ns + cb);
        I2[i]  = *(const __half2*)(nd + 128 + cb);
        I3s[i] = *(const __half2*)(ns + 256 + cb);
        I3d[i] = *(const __half2*)(nd + 256 + cb);
    }
    #pragma unroll
    for (int i = 0; i < 4; i++) {
        int e = ebase + i;
        float gt = sGate[e];
        float2 p1 = __half22float2(H1[i]);
        float2 p2 = __half22float2(H2[i]);
        float2 p3a = __half22float2(H3s[i]);
        float2 p3b = __half22float2(H3d[i]);
        float2 e3 = *(const float2*)&sRes[e * 68 + c];
        float2 u;
        u.x = gt * (p1.x + p2.x + e3.x + bu2.x);
        u.y = gt * (p1.y + p2.y + e3.y + bu2.y);
        *(float2*)&sUf[e * 64 + c] = u;
        __half2 uh = __floats2half2_rn(u.x, u.y);
        sAh[e * 36 + lane] = *(unsigned*)&uh;
        *(float2*)&sRes[e * 68 + c] = make_float2(p3a.x + p3b.x, p3a.y + p3b.y);
    }
    #pragma unroll
    for (int i = 0; i < 4; i++) {
        int e = ebase + 4 + i;
        float gt = sGate[e];
        float2 p1 = __half22float2(I1[i]);
        float2 p2 = __half22float2(I2[i]);
        float2 p3a = __half22float2(I3s[i]);
        float2 p3b = __half22float2(I3d[i]);
        float2 e3 = *(const float2*)&sRes[e * 68 + c];
        float2 u;
        u.x = gt * (p1.x + p2.x + e3.x + bu2.x);
        u.y = gt * (p1.y + p2.y + e3.y + bu2.y);
        *(float2*)&sUf[e * 64 + c] = u;
        __half2 uh = __floats2half2_rn(u.x, u.y);
        sAh[e * 36 + lane] = *(unsigned*)&uh;
        *(float2*)&sRes[e * 68 + c] = make_float2(p3a.x + p3b.x, p3a.y + p3b.y);
    }
    __syncthreads();

    // ---- MMA2 (fp16): T = updated @ W_edge; accumulate T into sRes (P3sum) ----
    #pragma unroll
    for (int nt = 0; nt < 4; nt++)
        #pragma unroll
        for (int j = 0; j < 4; j++) acc[nt][j] = 0.f;
    #pragma unroll
    for (int kk = 0; kk < 4; kk++) {
        unsigned a0 = sAh[(m0 + g)     * 36 + kk * 8 + q];
        unsigned a1 = sAh[(m0 + g + 8) * 36 + kk * 8 + q];
        unsigned a2 = sAh[(m0 + g)     * 36 + kk * 8 + q + 4];
        unsigned a3 = sAh[(m0 + g + 8) * 36 + kk * 8 + q + 4];
        int b8 = 512 + (ng * 4 + kk) * 64 + lane * 2;    // phase 1 (uint4 base = 512)
        uint4 w0 = __ldg(&Wh[b8]);
        uint4 w1 = __ldg(&Wh[b8 + 1]);
        mma_f16(acc[0], a0, a1, a2, a3, w0.x, w0.y);
        mma_f16(acc[1], a0, a1, a2, a3, w0.z, w0.w);
        mma_f16(acc[2], a0, a1, a2, a3, w1.x, w1.y);
        mma_f16(acc[3], a0, a1, a2, a3, w1.z, w1.w);
    }
    // no sync needed: += reads sRes (P3sum) ordered by the pre-MMA2 sync;
    // each element written by exactly one thread here.
    #pragma unroll
    for (int nt = 0; nt < 4; nt++) {
        int col = n0 + nt * 8 + q * 2;
        sRes[(m0 + g)     * 68 + col]     += acc[nt][0];
        sRes[(m0 + g)     * 68 + col + 1] += acc[nt][1];
        sRes[(m0 + g + 8) * 68 + col]     += acc[nt][2];
        sRes[(m0 + g + 8) * 68 + col + 1] += acc[nt][3];
    }
    __syncthreads();

    // ---- Phase B2: z = lrelu(sRes + cvec); softmax; store ----
    float2 zs[8];
    #pragma unroll
    for (int i = 0; i < 8; i++) {
        int e = ebase + i;
        bool v = (e0g + e) < E;
        float2 tv = *(const float2*)&sRes[e * 68 + c];
        float zx = lrelu_f(tv.x + cv2.x);
        float zy = lrelu_f(tv.y + cv2.y);
        zs[i] = v ? make_float2(zx, zy) : make_float2(-1e30f, -1e30f);
    }
    float2 ml = make_float2(-1e30f, -1e30f);
    #pragma unroll
    for (int i = 0; i < 8; i++) {
        ml.x = fmaxf(ml.x, zs[i].x);
        ml.y = fmaxf(ml.y, zs[i].y);
    }
    *(float2*)&sPM[warp * 68 + c] = ml;
    __syncthreads();
    float2 mb = make_float2(-1e30f, -1e30f);
    #pragma unroll
    for (int w2 = 0; w2 < 8; w2++) {
        mb.x = fmaxf(mb.x, sPM[w2 * 68 + c]);
        mb.y = fmaxf(mb.y, sPM[w2 * 68 + c + 1]);
    }
    float2 sl = make_float2(0.f, 0.f);
    #pragma unroll
    for (int i = 0; i < 8; i++) {
        int e = ebase + i;
        if ((e0g + e) < E) {
            float ex = __expf(zs[i].x - mb.x);
            float ey = __expf(zs[i].y - mb.y);
            sl.x += ex; sl.y += ey;
            float2 u = *(const float2*)&sUf[e * 64 + c];
            float2 o = make_float2(u.x * ex, u.y * ey);
            *(float2*)&out[(size_t)(e0g + e) * 64 + c] = o;
        }
    }
    *(float2*)&sPS[warp * 68 + c] = sl;
    __syncthreads();
    if (warp == 0) {
        float sx = 0.f, sy = 0.f;
        #pragma unroll
        for (int w2 = 0; w2 < 8; w2++) {
            sx += sPS[w2 * 68 + c];
            sy += sPS[w2 * 68 + c + 1];
        }
        g_partM[c * MAXNB + blockIdx.x]       = mb.x;
        g_partM[(c + 1) * MAXNB + blockIdx.x] = mb.y;
        g_partS[c * MAXNB + blockIdx.x]       = sx;
        g_partS[(c + 1) * MAXNB + blockIdx.x] = sy;
    }
}

__global__ void k_combine(int NB)
{
    int c = blockIdx.x, t = threadIdx.x;
    float m = -1e30f, s = 0.f;
    for (int b = t; b < NB; b += 256) {
        float mb = g_partM[c * MAXNB + b], sb = g_partS[c * MAXNB + b];
        float M2 = fmaxf(m, mb);
        s = s * __expf(m - M2) + sb * __expf(mb - M2);
        m = M2;
    }
    __shared__ float sm[256], ss[256];
    sm[t] = m; ss[t] = s; __syncthreads();
    for (int off = 128; off > 0; off >>= 1) {
        if (t < off) {
            float M2 = fmaxf(sm[t], sm[t + off]);
            ss[t] = ss[t] * __expf(sm[t] - M2) + ss[t + off] * __expf(sm[t + off] - M2);
            sm[t] = M2;
        }
        __syncthreads();
    }
    if (t == 0) { g_Mg[c] = sm[0]; g_invS[c] = 1.f / ss[0]; }
}

// factor table: g_factB[b*64 + c] = exp(m_blk - Mg) * invS
__global__ void k_fact(int NB)
{
    int idx = blockIdx.x * 256 + threadIdx.x;
    int b = idx >> 6, c = idx & 63;
    if (b >= NB) return;
    g_factB[(size_t)b * 64 + c] = __expf(g_partM[c * MAXNB + b] - g_Mg[c]) * g_invS[c];
}

// streaming rescale: one block per 64-edge tile; 64 factors staged in smem
__global__ __launch_bounds__(256) void k_pass2(float4* __restrict__ out, int E)
{
    __shared__ float sf[64];
    int b = blockIdx.x;
    int t = threadIdx.x;
    if (t < 64) sf[t] = g_factB[(size_t)b * 64 + t];
    __syncthreads();
    int base = b * 1024;
    #pragma unroll
    for (int r = 0; r < 4; r++) {
        int i = base + r * 256 + t;
        if ((i >> 4) < E) {
            int c0 = (i & 15) * 4;
            float4 o = out[i];
            o.x *= sf[c0]; o.y *= sf[c0 + 1]; o.z *= sf[c0 + 2]; o.w *= sf[c0 + 3];
            out[i] = o;
        }
    }
}

extern "C" void kernel_launch(void* const* d_in, const int* in_sizes, int n_in,
                              void* d_out, int out_size)
{
    const float* eemb = (const float*)d_in[0];
    const float* ne   = (const float*)d_in[2];
    const float* Wa   = (const float*)d_in[3];
    const float* ba   = (const float*)d_in[4];
    const float* Wu   = (const float*)d_in[5];
    const float* bu   = (const float*)d_in[6];
    const float* We   = (const float*)d_in[7];
    const float* be   = (const float*)d_in[8];
    const float* Wn   = (const float*)d_in[9];
    const float* bn   = (const float*)d_in[10];
    const void*  eidx = d_in[11];
    float* out = (float*)d_out;

    int E = in_sizes[0] / 64;
    int N = in_sizes[2] / 64;
    int NB = (E + 63) / 64;

    cudaFuncSetAttribute(k_edge, cudaFuncAttributeMaxDynamicSharedMemorySize, SMEM_BYTES);

    k_prep<<<1, 256>>>(Wa, ba, Wu, bu, We, be, Wn, bn, (const unsigned*)eidx);
    k_node<<<(N + 31) / 32, 256>>>(ne, N);
    k_mark<<<1, 64>>>();
    k_edge<<<NB, 256, SMEM_BYTES>>>(eemb, eidx, bu, out, E);
    k_combine<<<64, 256>>>(NB);
    k_fact<<<(NB * 64 + 255) / 256, 256>>>(NB);
    k_pass2<<<NB, 256>>>((float4*)out, E);
}

// round 14
// speedup vs baseline: 1.8769x; 1.0090x over previous
#include <cuda_runtime.h>
#include <cuda_fp16.h>

#define SLOPE 0.2f
#define NRB   576                  // node row: A[P1|P3 interleaved,256B] | B[P2|P3,256B] | a1,a2 | pad
#define MAXN  100352
#define MAXE  1000192
#define MAXNB (MAXE / 64)

__device__ float4   g_node[(size_t)MAXN * (NRB / 16)];   // 58MB, 576B/node
__device__ float    g_partM[64 * MAXNB];
__device__ float    g_partS[64 * MAXNB];
__device__ float    g_factB[(size_t)MAXNB * 64];
__device__ unsigned g_W2h[4096];    // k_edge weights fp16, fragment-major [ph][ng][kk(4)][lane][8]
__device__ unsigned g_Wnf[16384];   // k_node weights tf32, fragment-major [ng(4)][kk(8)][lane(32)][16]
__device__ float    g_Wa3[64];
__device__ float    g_cvec[64];
__device__ float    g_Mg[64];
__device__ float    g_invS[64];
__device__ float    g_battn;
__device__ int      g_idx64;

__device__ __forceinline__ float lrelu_f(float x) { return x >= 0.f ? x : SLOPE * x; }
__device__ __forceinline__ unsigned f2tf32(float f) {
    unsigned u; asm("cvt.rna.tf32.f32 %0, %1;" : "=r"(u) : "f"(f)); return u;
}
__device__ __forceinline__ void mma_tf32(float* c, unsigned a0, unsigned a1, unsigned a2, unsigned a3,
                                         unsigned b0, unsigned b1) {
    asm volatile("mma.sync.aligned.m16n8k8.row.col.f32.tf32.tf32.f32 "
                 "{%0,%1,%2,%3}, {%4,%5,%6,%7}, {%8,%9}, {%0,%1,%2,%3};"
                 : "+f"(c[0]), "+f"(c[1]), "+f"(c[2]), "+f"(c[3])
                 : "r"(a0), "r"(a1), "r"(a2), "r"(a3), "r"(b0), "r"(b1));
}
__device__ __forceinline__ void mma_f16(float* c, unsigned a0, unsigned a1, unsigned a2, unsigned a3,
                                        unsigned b0, unsigned b1) {
    asm volatile("mma.sync.aligned.m16n8k16.row.col.f32.f16.f16.f32 "
                 "{%0,%1,%2,%3}, {%4,%5,%6,%7}, {%8,%9}, {%0,%1,%2,%3};"
                 : "+f"(c[0]), "+f"(c[1]), "+f"(c[2]), "+f"(c[3])
                 : "r"(a0), "r"(a1), "r"(a2), "r"(a3), "r"(b0), "r"(b1));
}

__device__ __forceinline__ float wn_val(int k, int col,
                                        const float* W_upd, const float* W_node, const float* W_attn)
{
    if (col < 64)   return W_upd[k * 64 + col];
    if (col < 128)  return W_upd[(64 + k) * 64 + (col - 64)];
    if (col < 192)  return W_node[k * 64 + (col - 128)];
    if (col == 192) return W_attn[k];
    if (col == 193) return W_attn[64 + k];
    return 0.f;
}

__global__ void k_prep(const float* __restrict__ W_attn, const float* __restrict__ b_attn,
                       const float* __restrict__ W_upd,  const float* __restrict__ b_upd,
                       const float* __restrict__ W_edge, const float* __restrict__ b_edge,
                       const float* __restrict__ W_node, const float* __restrict__ b_node,
                       const unsigned* __restrict__ eidx_raw)
{
    int t = threadIdx.x;
    for (int idx = t; idx < 4096; idx += 256) {
        int r    = idx & 7;
        int lane = (idx >> 3) & 31;
        int kk   = (idx >> 8) & 3;
        int ng   = (idx >> 10) & 1;
        int ph   = (idx >> 11) & 1;
        int g = lane >> 2, q = lane & 3;
        int nt = r >> 1, hb = r & 1;
        int kb = kk * 16 + 2 * q + hb * 8;
        int c  = ng * 32 + nt * 8 + g;
        float v0 = (ph == 0) ? W_upd[(128 + kb) * 64 + c]     : W_edge[kb * 64 + c];
        float v1 = (ph == 0) ? W_upd[(128 + kb + 1) * 64 + c] : W_edge[(kb + 1) * 64 + c];
        __half2 h = __floats2half2_rn(v0, v1);
        g_W2h[idx] = *(unsigned*)&h;
    }
    for (int idx = t; idx < 16384; idx += 256) {
        int j    = idx & 15;
        int lane = (idx >> 4) & 31;
        int kk   = (idx >> 9) & 7;
        int ng   = (idx >> 12) & 3;
        float v = 0.f;
        if (j < 14) {
            int g = lane >> 2, q = lane & 3;
            int nt = j >> 1, b = j & 1;
            int k = kk * 8 + q + b * 4;
            int col = ng * 56 + nt * 8 + g;
            v = wn_val(k, col, W_upd, W_node, W_attn);
        }
        g_Wnf[idx] = f2tf32(v);
    }
    if (t < 64) {
        g_cvec[t] = b_edge[t] + 2.f * b_node[t];
        g_Wa3[t]  = W_attn[128 + t];
    }
    if (t == 0) {
        g_battn = b_attn[0];
        int is64 = 1;
        for (int i = 0; i < 32; i++)
            if (eidx_raw[2 * i + 1] != 0u) { is64 = 0; break; }
        g_idx64 = is64;
    }
}

// tf32 MMA node precompute: 32 nodes/block, 194 used cols, K=64
__global__ __launch_bounds__(256) void k_node(const float* __restrict__ ne, int N)
{
    __shared__ unsigned sX[32 * 68];
    __shared__ float    sOut[32 * 228];
    int t = threadIdx.x;
    int n0 = blockIdx.x * 32;

    for (int i = t; i < 32 * 64; i += 256) {
        int n = n0 + (i >> 6);
        float v = (n < N) ? ne[(size_t)n * 64 + (i & 63)] : 0.f;
        sX[(i >> 6) * 68 + (i & 63)] = f2tf32(v);
    }
    __syncthreads();

    int lane = t & 31, warp = t >> 5;
    int m0 = (warp & 1) * 16;
    int ng = warp >> 1;
    int n0c = ng * 56;
    int g = lane >> 2, q = lane & 3;
    const uint4* W4 = (const uint4*)g_Wnf;
    const uint2* W2 = (const uint2*)g_Wnf;

    float acc[7][4];
    #pragma unroll
    for (int nt = 0; nt < 7; nt++)
        #pragma unroll
        for (int j = 0; j < 4; j++) acc[nt][j] = 0.f;

    #pragma unroll
    for (int kk = 0; kk < 8; kk++) {
        unsigned a0 = sX[(m0 + g)     * 68 + kk * 8 + q];
        unsigned a1 = sX[(m0 + g + 8) * 68 + kk * 8 + q];
        unsigned a2 = sX[(m0 + g)     * 68 + kk * 8 + q + 4];
        unsigned a3 = sX[(m0 + g + 8) * 68 + kk * 8 + q + 4];
        int base = ((ng * 8 + kk) * 32 + lane);
        uint4 w0 = __ldg(&W4[base * 4]);
        uint4 w1 = __ldg(&W4[base * 4 + 1]);
        uint4 w2 = __ldg(&W4[base * 4 + 2]);
        uint2 w3 = __ldg(&W2[base * 8 + 6]);
        mma_tf32(acc[0], a0, a1, a2, a3, w0.x, w0.y);
        mma_tf32(acc[1], a0, a1, a2, a3, w0.z, w0.w);
        mma_tf32(acc[2], a0, a1, a2, a3, w1.x, w1.y);
        mma_tf32(acc[3], a0, a1, a2, a3, w1.z, w1.w);
        mma_tf32(acc[4], a0, a1, a2, a3, w2.x, w2.y);
        mma_tf32(acc[5], a0, a1, a2, a3, w2.z, w2.w);
        mma_tf32(acc[6], a0, a1, a2, a3, w3.x, w3.y);
    }
    #pragma unroll
    for (int nt = 0; nt < 7; nt++) {
        int col = n0c + nt * 8 + q * 2;
        sOut[(m0 + g)     * 228 + col]     = acc[nt][0];
        sOut[(m0 + g)     * 228 + col + 1] = acc[nt][1];
        sOut[(m0 + g + 8) * 228 + col]     = acc[nt][2];
        sOut[(m0 + g + 8) * 228 + col + 1] = acc[nt][3];
    }
    __syncthreads();

    // pack interleaved fp16 node table: A[j*8]={P1,P3}, B[256+j*8]={P2,P3}
    for (int i = t; i < 32 * 32; i += 256) {
        int n = i >> 5, j = i & 31;
        if (n0 + n >= N) continue;
        char* dst = (char*)g_node + (size_t)(n0 + n) * NRB;
        __half2 p1 = __floats2half2_rn(sOut[n * 228 + 2 * j],       sOut[n * 228 + 2 * j + 1]);
        __half2 p2 = __floats2half2_rn(sOut[n * 228 + 64 + 2 * j],  sOut[n * 228 + 65 + 2 * j]);
        __half2 p3 = __floats2half2_rn(sOut[n * 228 + 128 + 2 * j], sOut[n * 228 + 129 + 2 * j]);
        uint2 ra = make_uint2(*(unsigned*)&p1, *(unsigned*)&p3);
        uint2 rb = make_uint2(*(unsigned*)&p2, *(unsigned*)&p3);
        *(uint2*)(dst + j * 8)       = ra;
        *(uint2*)(dst + 256 + j * 8) = rb;
    }
    if (t < 32 && n0 + t < N) {
        char* dst = (char*)g_node + (size_t)(n0 + t) * NRB;
        *(float*)(dst + 512) = sOut[t * 228 + 192];
        *(float*)(dst + 516) = sOut[t * 228 + 193];
    }
}

// dummy kernel — keeps k_edge in the fixed ncu capture slot
__global__ void k_mark() { if (threadIdx.x < 64) g_Mg[threadIdx.x] = 0.f; }

// smem (u32): sAh[64*36] fp16 tile | sRes[64*68] | sUf[64*64] | sPM[8*68] | sPS[8*68] | misc
#define SAH_U (64 * 36)
#define SR_F  (64 * 68)
#define SUF_F (64 * 64)
#define SP_F  (8 * 68)
#define SMEM_F (SAH_U + SR_F + SUF_F + 2 * SP_F + 256)
#define SMEM_BYTES (SMEM_F * 4)

__global__ __launch_bounds__(256, 4) void k_edge(const float* __restrict__ eemb,
                                                 const void*  __restrict__ eidx,
                                                 const float* __restrict__ bupd,
                                                 float*       __restrict__ out,
                                                 int E)
{
    extern __shared__ float smem[];
    unsigned* sAh   = (unsigned*)smem;       // fp16: edge tile → updated
    float*    sRes  = smem + SAH_U;          // E3 → P3sum → P3sum+T
    float*    sUf   = smem + SAH_U + SR_F;   // updated fp32 (pitch 64)
    float*    sPM   = smem + SAH_U + SR_F + SUF_F;
    float*    sPS   = sPM + SP_F;
    float*    sWa   = sPS + SP_F;
    float*    sGate = sWa + 64;
    int*      sSrc  = (int*)(sGate + 64);    // byte offsets into g_node
    int*      sDst  = sSrc + 64;

    int t = threadIdx.x;
    int e0g = blockIdx.x * 64;
    int idx64 = g_idx64;

    if (t < 128) {
        int j = t & 63;
        int ee = min(e0g + j, E - 1);
        size_t pos = (t < 64) ? (size_t)ee : (size_t)E + (size_t)ee;
        int v = idx64 ? (int)((const long long*)eidx)[pos] : ((const int*)eidx)[pos];
        if (t < 64) sSrc[j] = v * NRB; else sDst[j] = v * NRB;
    }
    if (t >= 128 && t < 192) sWa[t - 128] = g_Wa3[t - 128];
    for (int i = t; i < 64 * 32; i += 256) {
        int e = i >> 5, k2 = i & 31;
        int ee = min(e0g + e, E - 1);
        float2 v = __ldcs((const float2*)(eemb + (size_t)ee * 64 + k2 * 2));
        __half2 h = __floats2half2_rn(v.x, v.y);
        sAh[e * 36 + k2] = *(unsigned*)&h;
    }
    __syncthreads();

    int lane = t & 31, warp = t >> 5;
    int m0 = (warp & 3) * 16;
    int ng = warp >> 2;
    int n0 = ng * 32;
    int g = lane >> 2, q = lane & 3;
    const uint4* Wh = (const uint4*)g_W2h;    // 1024 uint4; phase1 starts at 512
    const char* nb = (const char*)g_node;

    int c = lane * 2;
    int cb = lane * 8;               // uint2 byte offset within region
    int ebase = warp * 8;

    // ---- prefetch gathers for edges ebase..ebase+3 (overlap with MMA1) ----
    uint2 S1[4], D1[4];
    #pragma unroll
    for (int i = 0; i < 4; i++) {
        int e = ebase + i;
        S1[i] = *(const uint2*)(nb + sSrc[e] + cb);          // {P1, P3s}
        D1[i] = *(const uint2*)(nb + sDst[e] + 256 + cb);    // {P2, P3d}
    }

    // ---- MMA1 (fp16, K=16/step): E3 = A @ Wu3 ----
    float acc[4][4];
    #pragma unroll
    for (int nt = 0; nt < 4; nt++)
        #pragma unroll
        for (int j = 0; j < 4; j++) acc[nt][j] = 0.f;
    #pragma unroll
    for (int kk = 0; kk < 4; kk++) {
        unsigned a0 = sAh[(m0 + g)     * 36 + kk * 8 + q];
        unsigned a1 = sAh[(m0 + g + 8) * 36 + kk * 8 + q];
        unsigned a2 = sAh[(m0 + g)     * 36 + kk * 8 + q + 4];
        unsigned a3 = sAh[(m0 + g + 8) * 36 + kk * 8 + q + 4];
        int b8 = (ng * 4 + kk) * 64 + lane * 2;
        uint4 w0 = __ldg(&Wh[b8]);
        uint4 w1 = __ldg(&Wh[b8 + 1]);
        mma_f16(acc[0], a0, a1, a2, a3, w0.x, w0.y);
        mma_f16(acc[1], a0, a1, a2, a3, w0.z, w0.w);
        mma_f16(acc[2], a0, a1, a2, a3, w1.x, w1.y);
        mma_f16(acc[3], a0, a1, a2, a3, w1.z, w1.w);
    }
    #pragma unroll
    for (int nt = 0; nt < 4; nt++) {
        int col = n0 + nt * 8 + q * 2;
        sRes[(m0 + g)     * 68 + col]     = acc[nt][0];
        sRes[(m0 + g)     * 68 + col + 1] = acc[nt][1];
        sRes[(m0 + g + 8) * 68 + col]     = acc[nt][2];
        sRes[(m0 + g + 8) * 68 + col + 1] = acc[nt][3];
    }
    // gate (reads fp16 edge tile)
    if (t < 64) {
        float s = 0.f;
        #pragma unroll 8
        for (int k2 = 0; k2 < 32; k2++) {
            unsigned hb = sAh[t * 36 + k2];
            float2 a = __half22float2(*(__half2*)&hb);
            s += a.x * sWa[2 * k2] + a.y * sWa[2 * k2 + 1];
        }
        float a1v = *(const float*)(nb + sSrc[t] + 512);
        float a2v = *(const float*)(nb + sDst[t] + 516);
        sGate[t] = 1.f / (1.f + __expf(-lrelu_f(a1v + a2v + s + g_battn)));
    }
    __syncthreads();

    // ---- Phase B1: prefetched batch + pipelined second batch ----
    float2 bu2 = make_float2(bupd[c], bupd[c + 1]);
    float2 cv2 = make_float2(g_cvec[c], g_cvec[c + 1]);

    uint2 S2[4], D2[4];
    #pragma unroll
    for (int i = 0; i < 4; i++) {
        int e = ebase + 4 + i;
        S2[i] = *(const uint2*)(nb + sSrc[e] + cb);
        D2[i] = *(const uint2*)(nb + sDst[e] + 256 + cb);
    }
    #pragma unroll
    for (int i = 0; i < 4; i++) {
        int e = ebase + i;
        float gt = sGate[e];
        float2 p1  = __half22float2(*(__half2*)&S1[i].x);
        float2 p3a = __half22float2(*(__half2*)&S1[i].y);
        float2 p2  = __half22float2(*(__half2*)&D1[i].x);
        float2 p3b = __half22float2(*(__half2*)&D1[i].y);
        float2 e3 = *(const float2*)&sRes[e * 68 + c];
        float2 u;
        u.x = gt * (p1.x + p2.x + e3.x + bu2.x);
        u.y = gt * (p1.y + p2.y + e3.y + bu2.y);
        *(float2*)&sUf[e * 64 + c] = u;
        __half2 uh = __floats2half2_rn(u.x, u.y);
        sAh[e * 36 + lane] = *(unsigned*)&uh;
        *(float2*)&sRes[e * 68 + c] = make_float2(p3a.x + p3b.x, p3a.y + p3b.y);
    }
    #pragma unroll
    for (int i = 0; i < 4; i++) {
        int e = ebase + 4 + i;
        float gt = sGate[e];
        float2 p1  = __half22float2(*(__half2*)&S2[i].x);
        float2 p3a = __half22float2(*(__half2*)&S2[i].y);
        float2 p2  = __half22float2(*(__half2*)&D2[i].x);
        float2 p3b = __half22float2(*(__half2*)&D2[i].y);
        float2 e3 = *(const float2*)&sRes[e * 68 + c];
        float2 u;
        u.x = gt * (p1.x + p2.x + e3.x + bu2.x);
        u.y = gt * (p1.y + p2.y + e3.y + bu2.y);
        *(float2*)&sUf[e * 64 + c] = u;
        __half2 uh = __floats2half2_rn(u.x, u.y);
        sAh[e * 36 + lane] = *(unsigned*)&uh;
        *(float2*)&sRes[e * 68 + c] = make_float2(p3a.x + p3b.x, p3a.y + p3b.y);
    }
    __syncthreads();

    // ---- MMA2 (fp16): T = updated @ W_edge; accumulate T into sRes (P3sum) ----
    #pragma unroll
    for (int nt = 0; nt < 4; nt++)
        #pragma unroll
        for (int j = 0; j < 4; j++) acc[nt][j] = 0.f;
    #pragma unroll
    for (int kk = 0; kk < 4; kk++) {
        unsigned a0 = sAh[(m0 + g)     * 36 + kk * 8 + q];
        unsigned a1 = sAh[(m0 + g + 8) * 36 + kk * 8 + q];
        unsigned a2 = sAh[(m0 + g)     * 36 + kk * 8 + q + 4];
        unsigned a3 = sAh[(m0 + g + 8) * 36 + kk * 8 + q + 4];
        int b8 = 512 + (ng * 4 + kk) * 64 + lane * 2;
        uint4 w0 = __ldg(&Wh[b8]);
        uint4 w1 = __ldg(&Wh[b8 + 1]);
        mma_f16(acc[0], a0, a1, a2, a3, w0.x, w0.y);
        mma_f16(acc[1], a0, a1, a2, a3, w0.z, w0.w);
        mma_f16(acc[2], a0, a1, a2, a3, w1.x, w1.y);
        mma_f16(acc[3], a0, a1, a2, a3, w1.z, w1.w);
    }
    #pragma unroll
    for (int nt = 0; nt < 4; nt++) {
        int col = n0 + nt * 8 + q * 2;
        sRes[(m0 + g)     * 68 + col]     += acc[nt][0];
        sRes[(m0 + g)     * 68 + col + 1] += acc[nt][1];
        sRes[(m0 + g + 8) * 68 + col]     += acc[nt][2];
        sRes[(m0 + g + 8) * 68 + col + 1] += acc[nt][3];
    }
    __syncthreads();

    // ---- Phase B2: z = lrelu(sRes + cvec); softmax; store ----
    float2 zs[8];
    #pragma unroll
    for (int i = 0; i < 8; i++) {
        int e = ebase + i;
        bool v = (e0g + e) < E;
        float2 tv = *(const float2*)&sRes[e * 68 + c];
        float zx = lrelu_f(tv.x + cv2.x);
        float zy = lrelu_f(tv.y + cv2.y);
        zs[i] = v ? make_float2(zx, zy) : make_float2(-1e30f, -1e30f);
    }
    float2 ml = make_float2(-1e30f, -1e30f);
    #pragma unroll
    for (int i = 0; i < 8; i++) {
        ml.x = fmaxf(ml.x, zs[i].x);
        ml.y = fmaxf(ml.y, zs[i].y);
    }
    *(float2*)&sPM[warp * 68 + c] = ml;
    __syncthreads();
    float2 mb = make_float2(-1e30f, -1e30f);
    #pragma unroll
    for (int w2 = 0; w2 < 8; w2++) {
        mb.x = fmaxf(mb.x, sPM[w2 * 68 + c]);
        mb.y = fmaxf(mb.y, sPM[w2 * 68 + c + 1]);
    }
    float2 sl = make_float2(0.f, 0.f);
    #pragma unroll
    for (int i = 0; i < 8; i++) {
        int e = ebase + i;
        if ((e0g + e) < E) {
            float ex = __expf(zs[i].x - mb.x);
            float ey = __expf(zs[i].y - mb.y);
            sl.x += ex; sl.y += ey;
            float2 u = *(const float2*)&sUf[e * 64 + c];
            float2 o = make_float2(u.x * ex, u.y * ey);
            __stcs((float2*)&out[(size_t)(e0g + e) * 64 + c], o);
        }
    }
    *(float2*)&sPS[warp * 68 + c] = sl;
    __syncthreads();
    if (warp == 0) {
        float sx = 0.f, sy = 0.f;
        #pragma unroll
        for (int w2 = 0; w2 < 8; w2++) {
            sx += sPS[w2 * 68 + c];
            sy += sPS[w2 * 68 + c + 1];
        }
        g_partM[c * MAXNB + blockIdx.x]       = mb.x;
        g_partM[(c + 1) * MAXNB + blockIdx.x] = mb.y;
        g_partS[c * MAXNB + blockIdx.x]       = sx;
        g_partS[(c + 1) * MAXNB + blockIdx.x] = sy;
    }
}

__global__ void k_combine(int NB)
{
    int c = blockIdx.x, t = threadIdx.x;
    float m = -1e30f, s = 0.f;
    for (int b = t; b < NB; b += 256) {
        float mb = g_partM[c * MAXNB + b], sb = g_partS[c * MAXNB + b];
        float M2 = fmaxf(m, mb);
        s = s * __expf(m - M2) + sb * __expf(mb - M2);
        m = M2;
    }
    __shared__ float sm[256], ss[256];
    sm[t] = m; ss[t] = s; __syncthreads();
    for (int off = 128; off > 0; off >>= 1) {
        if (t < off) {
            float M2 = fmaxf(sm[t], sm[t + off]);
            ss[t] = ss[t] * __expf(sm[t] - M2) + ss[t + off] * __expf(sm[t + off] - M2);
            sm[t] = M2;
        }
        __syncthreads();
    }
    if (t == 0) { g_Mg[c] = sm[0]; g_invS[c] = 1.f / ss[0]; }
}

__global__ void k_fact(int NB)
{
    int idx = blockIdx.x * 256 + threadIdx.x;
    int b = idx >> 6, c = idx & 63;
    if (b >= NB) return;
    g_factB[(size_t)b * 64 + c] = __expf(g_partM[c * MAXNB + b] - g_Mg[c]) * g_invS[c];
}

__global__ __launch_bounds__(256) void k_pass2(float4* __restrict__ out, int E)
{
    __shared__ float sf[64];
    int b = blockIdx.x;
    int t = threadIdx.x;
    if (t < 64) sf[t] = g_factB[(size_t)b * 64 + t];
    __syncthreads();
    int base = b * 1024;
    #pragma unroll
    for (int r = 0; r < 4; r++) {
        int i = base + r * 256 + t;
        if ((i >> 4) < E) {
            int c0 = (i & 15) * 4;
            float4 o = __ldcs(&out[i]);
            o.x *= sf[c0]; o.y *= sf[c0 + 1]; o.z *= sf[c0 + 2]; o.w *= sf[c0 + 3];
            __stcs(&out[i], o);
        }
    }
}

extern "C" void kernel_launch(void* const* d_in, const int* in_sizes, int n_in,
                              void* d_out, int out_size)
{
    const float* eemb = (const float*)d_in[0];
    const float* ne   = (const float*)d_in[2];
    const float* Wa   = (const float*)d_in[3];
    const float* ba   = (const float*)d_in[4];
    const float* Wu   = (const float*)d_in[5];
    const float* bu   = (const float*)d_in[6];
    const float* We   = (const float*)d_in[7];
    const float* be   = (const float*)d_in[8];
    const float* Wn   = (const float*)d_in[9];
    const float* bn   = (const float*)d_in[10];
    const void*  eidx = d_in[11];
    float* out = (float*)d_out;

    int E = in_sizes[0] / 64;
    int N = in_sizes[2] / 64;
    int NB = (E + 63) / 64;

    cudaFuncSetAttribute(k_edge, cudaFuncAttributeMaxDynamicSharedMemorySize, SMEM_BYTES);

    k_prep<<<1, 256>>>(Wa, ba, Wu, bu, We, be, Wn, bn, (const unsigned*)eidx);
    k_node<<<(N + 31) / 32, 256>>>(ne, N);
    k_mark<<<1, 64>>>();
    k_edge<<<NB, 256, SMEM_BYTES>>>(eemb, eidx, bu, out, E);
    k_combine<<<64, 256>>>(NB);
    k_fact<<<(NB * 64 + 255) / 256, 256>>>(NB);
    k_pass2<<<NB, 256>>>((float4*)out, E);
}